// round 14
// baseline (speedup 1.0000x reference)
#include <cuda_runtime.h>
#include <cuda_fp16.h>
#include <mma.h>
#include <stdint.h>

using namespace nvcuda;

// Model dims
constexpr int B = 32, T = 40, P = 256, V = 4096, D = 256, DINO = 384, H = 4, L = 2;
constexpr int HD = 64, DFF = 1024;
constexpr float EPS = 1e-5f;
constexpr int M_ENC = B * T;  // 1280

// ---------------- fp32 scratch ----------------
__device__ float g_x[M_ENC * D];
__device__ float g_y[M_ENC * D];
__device__ float g_pproj[B * P * D];
__device__ float g_cproj[M_ENC * D];
__device__ float g_u[M_ENC * D];
__device__ float g_c0[M_ENC];

// ---------------- fp16 scratch ----------------
__device__ __half g_xh[M_ENC * D];
__device__ __half g_qkvh[M_ENC * 3 * D];
__device__ __half g_ctxh[M_ENC * D];
__device__ __half g_hh[M_ENC * DFF];
__device__ __half g_ph[B * P * DINO];
__device__ __half g_qkvwh[L * 3 * D * D];
__device__ __half g_outwh[L * D * D];
__device__ __half g_w1h[L * DFF * D];
__device__ __half g_w2h[L * D * DFF];
__device__ __half g_fw1h[D * (DINO + D)];

// ---------------- helpers ----------------
__device__ __forceinline__ uint32_t smem_u32(const void* p) {
    uint32_t a;
    asm("{ .reg .u64 t; cvta.to.shared.u64 t, %1; cvt.u32.u64 %0, t; }" : "=r"(a) : "l"(p));
    return a;
}
__device__ __forceinline__ void cpa16(uint32_t dst, const void* src, int sz) {
    asm volatile("cp.async.cg.shared.global [%0], [%1], 16, %2;" :: "r"(dst), "l"(src), "r"(sz));
}
__device__ __forceinline__ void cpa_commit() { asm volatile("cp.async.commit_group;"); }

__device__ __forceinline__ __half2 htanh2(__half2 x) {
    uint32_t xi = *reinterpret_cast<uint32_t*>(&x);
    uint32_t ri;
    asm("tanh.approx.f16x2 %0, %1;" : "=r"(ri) : "r"(xi));
    return *reinterpret_cast<__half2*>(&ri);
}

__device__ __forceinline__ void cvt4(float4 v, __half* d, size_t off) {
    *reinterpret_cast<__half2*>(&d[off]) = __floats2half2_rn(v.x, v.y);
    *reinterpret_cast<__half2*>(&d[off + 2]) = __floats2half2_rn(v.z, v.w);
}

// ---------------- prep MAIN: embed + L0 qkv weights + out_w (both) -> fp16 ----------------
__global__ void __launch_bounds__(256) prep_main_kernel(
    const float* __restrict__ qkv_w, const float* __restrict__ out_w,
    const int* __restrict__ tokens, const float* __restrict__ tok_emb,
    const float* __restrict__ pos_emb) {
    constexpr int SQ0 = 3 * D * D / 4;
    constexpr int SO = L * D * D / 4;
    constexpr int S7 = M_ENC * D / 4;
    constexpr int TOT = SQ0 + SO + S7;
    for (int i = blockIdx.x * blockDim.x + threadIdx.x; i < TOT; i += gridDim.x * blockDim.x) {
        int j = i;
        if (j < SQ0) {
            float4 v = *reinterpret_cast<const float4*>(&qkv_w[(size_t)j * 4]);
            cvt4(v, g_qkvwh, (size_t)j * 4);
        } else if ((j -= SQ0) < SO) {
            float4 v = *reinterpret_cast<const float4*>(&out_w[(size_t)j * 4]);
            cvt4(v, g_outwh, (size_t)j * 4);
        } else {
            j -= SO;
            int bt = (j * 4) >> 8;
            int d0 = (j * 4) & 255;
            int t = bt % T;
            float4 te = *reinterpret_cast<const float4*>(&tok_emb[(size_t)tokens[bt] * D + d0]);
            float4 pe = *reinterpret_cast<const float4*>(&pos_emb[(size_t)t * D + d0]);
            float4 v = make_float4(te.x + pe.x, te.y + pe.y, te.z + pe.z, te.w + pe.w);
            *reinterpret_cast<float4*>(&g_x[(size_t)j * 4]) = v;
            cvt4(v, g_xh, (size_t)j * 4);
        }
    }
}

// ---------------- prep REST: L1 qkv weights + w1 + w2 -> fp16 (side stream) --------
__global__ void __launch_bounds__(256) prep_rest_kernel(
    const float* __restrict__ qkv_w,
    const float* __restrict__ w1, const float* __restrict__ w2) {
    constexpr int SQ1 = 3 * D * D / 4;
    constexpr int S3 = L * DFF * D / 4;
    constexpr int S4 = L * D * DFF / 4;
    constexpr int TOT = SQ1 + S3 + S4;
    for (int i = blockIdx.x * blockDim.x + threadIdx.x; i < TOT; i += gridDim.x * blockDim.x) {
        int j = i;
        const float* src;
        __half* dh;
        size_t base = 0;
        if (j < SQ1) { src = qkv_w; dh = g_qkvwh; base = (size_t)SQ1 * 4; }
        else if ((j -= SQ1) < S3) { src = w1; dh = g_w1h; }
        else { j -= S3; src = w2; dh = g_w2h; }
        float4 v = *reinterpret_cast<const float4*>(&src[base + (size_t)j * 4]);
        cvt4(v, dh, base + (size_t)j * 4);
    }
}

// ---------------- prep B: fusion weights + patches -> fp16 ----------------
__global__ void __launch_bounds__(256) prep_fus_kernel(
    const float* __restrict__ fus_w1, const float* __restrict__ patches) {
    constexpr int S5 = D * (DINO + D) / 4;
    constexpr int S6 = B * P * DINO / 4;
    constexpr int TOT = S5 + S6;
    for (int i = blockIdx.x * blockDim.x + threadIdx.x; i < TOT; i += gridDim.x * blockDim.x) {
        int j = i;
        const float* src;
        __half* dh;
        if (j < S5) { src = fus_w1; dh = g_fw1h; }
        else { j -= S5; src = patches; dh = g_ph; }
        float4 v = *reinterpret_cast<const float4*>(&src[(size_t)j * 4]);
        cvt4(v, dh, (size_t)j * 4);
    }
}

// ======================= fp16 GEMM, 3-stage; optional fused-LN A staging =======================
// Normal: A fp16 [lda], staged per-chunk alongside W (pair layout, 3 bufs).
// LNSTAGE (K must be 256): A = LN(A32 row) computed in-kernel; A occupies 4 fixed chunk
// buffers; W cycles 3 bufs after them. SHIFT (with LNSTAGE): row bt uses A32 row bt-1, zeros at t==0.
// n0==0 CTAs (LNSTAGE, !SHIFT) also write pxout (fp32 LN result) for residual consumers.
constexpr int BM = 64, BN = 64, BK = 64;
constexpr int LDTE = 72;
constexpr int TILEB = 64 * LDTE * 2;           // 9216 B
constexpr int NSTAGE = 3;
constexpr int GEMM_SMEM = NSTAGE * 2 * TILEB;  // 55296 (normal)
constexpr int GEMM_SMEM_LN = 7 * TILEB;        // 64512 (LNSTAGE: 4 A + 3 W)

template <bool BIAS, bool RES, bool RELU, bool EMIT32, bool EMITH, bool SHIFT, bool LNSTAGE>
__global__ void __launch_bounds__(256, 3) gemm_fp16(
    const __half* __restrict__ A, int lda,
    const float* __restrict__ A32, const float* __restrict__ lns, const float* __restrict__ lnb,
    float* __restrict__ pxout,
    const __half* __restrict__ W, int ldw,
    const float* __restrict__ bias, const float* __restrict__ res,
    float* __restrict__ C32, __half* __restrict__ Ch,
    int ldc, int K) {
    extern __shared__ char sm[];
    cudaGridDependencySynchronize();
    const int tid = threadIdx.x;
    const int n0 = blockIdx.x * BN;
    const int m0 = blockIdx.y * BM;
    const int nchunk = K / BK;
    const uint32_t sb0 = smem_u32(sm);

    auto stage = [&](int c) {
        const int k0 = c * BK;
        if (LNSTAGE) {
            const uint32_t sbase = sb0 + 4 * TILEB + (c % NSTAGE) * TILEB;
#pragma unroll
            for (int g = 0; g < 2; g++) {
                int gi = tid + g * 256;
                int row = gi >> 3, c16 = gi & 7;
                cpa16(sbase + row * 144 + c16 * 16,
                      W + (size_t)(n0 + row) * ldw + k0 + c16 * 8, 16);
            }
        } else {
            const uint32_t sbase = sb0 + (c % NSTAGE) * 2 * TILEB;
#pragma unroll
            for (int g = 0; g < 2; g++) {
                int gi = tid + g * 256;
                int row = gi >> 3, c16 = gi & 7;
                uint32_t soff = row * 144 + c16 * 16;
                cpa16(sbase + soff, A + (size_t)(m0 + row) * lda + k0 + c16 * 8, 16);
                cpa16(sbase + TILEB + soff, W + (size_t)(n0 + row) * ldw + k0 + c16 * 8, 16);
            }
        }
        cpa_commit();
    };

    stage(0);
    if (nchunk > 1) stage(1);

    if (LNSTAGE) {
        // phase 1: LN rows m0..m0+63 of A32 -> fp16 A chunks (overlaps W cp.async)
        const int r = tid >> 2;     // 0..63
        const int seg = tid & 3;    // 0..3 (64 cols each)
        const int arow = m0 + r;
        bool zrow = false;
        int srcrow = arow;
        if (SHIFT) { if (arow % T == 0) zrow = true; else srcrow = arow - 1; }
        const float* yrow = A32 + (size_t)srcrow * 256 + seg * 64;
        float s = 0.f, q = 0.f;
        if (!zrow) {
#pragma unroll
            for (int j = 0; j < 16; j++) {
                float4 v = *reinterpret_cast<const float4*>(yrow + j * 4);
                s += v.x + v.y + v.z + v.w;
                q += v.x * v.x + v.y * v.y + v.z * v.z + v.w * v.w;
            }
        }
        s += __shfl_xor_sync(0xffffffffu, s, 1);
        q += __shfl_xor_sync(0xffffffffu, q, 1);
        s += __shfl_xor_sync(0xffffffffu, s, 2);
        q += __shfl_xor_sync(0xffffffffu, q, 2);
        float mean = s * (1.f / 256.f);
        float rstd = rsqrtf(q * (1.f / 256.f) - mean * mean + EPS);
#pragma unroll
        for (int j = 0; j < 16; j++) {
            int col = seg * 64 + j * 4;
            int chunk = col >> 6, k = col & 63;
            char* base = sm + chunk * TILEB + r * 144 + (k >> 3) * 16 + (k & 7) * 2;
            if (zrow) {
                *reinterpret_cast<__half2*>(base) = __floats2half2_rn(0.f, 0.f);
                *reinterpret_cast<__half2*>(base + 4) = __floats2half2_rn(0.f, 0.f);
            } else {
                float4 v = *reinterpret_cast<const float4*>(yrow + j * 4);
                float4 sc = *reinterpret_cast<const float4*>(lns + col);
                float4 bi = *reinterpret_cast<const float4*>(lnb + col);
                float4 g;
                g.x = (v.x - mean) * rstd * sc.x + bi.x;
                g.y = (v.y - mean) * rstd * sc.y + bi.y;
                g.z = (v.z - mean) * rstd * sc.z + bi.z;
                g.w = (v.w - mean) * rstd * sc.w + bi.w;
                *reinterpret_cast<__half2*>(base) = __floats2half2_rn(g.x, g.y);
                *reinterpret_cast<__half2*>(base + 4) = __floats2half2_rn(g.z, g.w);
                if (!SHIFT && n0 == 0)
                    *reinterpret_cast<float4*>(&pxout[(size_t)arow * 256 + col]) = g;
            }
        }
    }

    const int w = tid >> 5;
    const int wm = w >> 2;
    const int wn = w & 3;

    wmma::fragment<wmma::accumulator, 16, 16, 16, float> acc[2];
    wmma::fill_fragment(acc[0], 0.f);
    wmma::fill_fragment(acc[1], 0.f);

    for (int c = 0; c < nchunk; c++) {
        if (c + 1 < nchunk) {
            asm volatile("cp.async.wait_group 1;");
        } else {
            asm volatile("cp.async.wait_group 0;");
        }
        __syncthreads();   // publishes chunk c (and phase-1 A writes on c==0)
        if (c + 2 < nchunk) stage(c + 2);
        const __half* tA;
        const __half* tW;
        if (LNSTAGE) {
            tA = reinterpret_cast<const __half*>(sm + c * TILEB);
            tW = reinterpret_cast<const __half*>(sm + 4 * TILEB + (c % NSTAGE) * TILEB);
        } else {
            char* bb = sm + (c % NSTAGE) * 2 * TILEB;
            tA = reinterpret_cast<const __half*>(bb);
            tW = reinterpret_cast<const __half*>(bb + TILEB);
        }
#pragma unroll
        for (int ks = 0; ks < 4; ks++) {
            wmma::fragment<wmma::matrix_b, 16, 16, 16, __half, wmma::col_major> bh;
            wmma::load_matrix_sync(bh, &tW[(wn * 16) * LDTE + ks * 16], LDTE);
            wmma::fragment<wmma::matrix_a, 16, 16, 16, __half, wmma::row_major> ah[2];
            wmma::load_matrix_sync(ah[0], &tA[(wm * 32) * LDTE + ks * 16], LDTE);
            wmma::load_matrix_sync(ah[1], &tA[(wm * 32 + 16) * LDTE + ks * 16], LDTE);
            wmma::mma_sync(acc[0], ah[0], bh, acc[0]);
            wmma::mma_sync(acc[1], ah[1], bh, acc[1]);
        }
    }
    __syncthreads();

    float* Cs = reinterpret_cast<float*>(sm);
    wmma::store_matrix_sync(&Cs[(wm * 32) * LDTE + wn * 16], acc[0], LDTE, wmma::mem_row_major);
    wmma::store_matrix_sync(&Cs[(wm * 32 + 16) * LDTE + wn * 16], acc[1], LDTE, wmma::mem_row_major);
    __syncthreads();

#pragma unroll
    for (int i = tid * 4; i < BM * BN; i += 1024) {
        int r = i >> 6, cc = i & 63;
        int m = m0 + r, n = n0 + cc;
        float4 v = *reinterpret_cast<const float4*>(&Cs[r * LDTE + cc]);
        if (BIAS) {
            float4 bv = *reinterpret_cast<const float4*>(&bias[n]);
            v.x += bv.x; v.y += bv.y; v.z += bv.z; v.w += bv.w;
        }
        if (RES) {
            float4 rv = *reinterpret_cast<const float4*>(&res[(size_t)m * ldc + n]);
            v.x += rv.x; v.y += rv.y; v.z += rv.z; v.w += rv.w;
        }
        if (RELU) {
            v.x = fmaxf(v.x, 0.f); v.y = fmaxf(v.y, 0.f);
            v.z = fmaxf(v.z, 0.f); v.w = fmaxf(v.w, 0.f);
        }
        if (EMIT32) *reinterpret_cast<float4*>(&C32[(size_t)m * ldc + n]) = v;
        if (EMITH) {
            *reinterpret_cast<__half2*>(&Ch[(size_t)m * ldc + n]) = __floats2half2_rn(v.x, v.y);
            *reinterpret_cast<__half2*>(&Ch[(size_t)m * ldc + n + 2]) = __floats2half2_rn(v.z, v.w);
        }
    }
}

// ---------------- attention (fp16 qkv in, fp16 ctx out) ----------------
__global__ void __launch_bounds__(256) attn_kernel(const __half* __restrict__ qkv,
                                                   __half* __restrict__ ctxh) {
    cudaGridDependencySynchronize();
    int bh = blockIdx.x;
    int b = bh / H;
    int h = bh % H;
    __shared__ float Ks[T][HD + 1];
    __shared__ float Vs[T][HD + 1];
    __shared__ float Qs[8][HD];
    __shared__ float Ps[8][T];
    int tid = threadIdx.x;
    int w = tid >> 5, lane = tid & 31;
    for (int i = tid; i < T * HD; i += 256) {
        int t = i >> 6, d = i & 63;
        size_t base = ((size_t)(b * T + t)) * (3 * D) + h * HD + d;
        Ks[t][d] = __half2float(qkv[base + D]);
        Vs[t][d] = __half2float(qkv[base + 2 * D]);
    }
    __syncthreads();
    for (int r = w; r < T; r += 8) {
        size_t qb = ((size_t)(b * T + r)) * (3 * D) + h * HD;
        Qs[w][lane] = __half2float(qkv[qb + lane]);
        Qs[w][lane + 32] = __half2float(qkv[qb + lane + 32]);
        __syncwarp();
        int k0 = lane, k1 = lane + 32;
        float s0 = -1e30f, s1 = -1e30f;
        if (k0 <= r) {
            float a = 0.f;
#pragma unroll
            for (int d = 0; d < HD; d++) a += Qs[w][d] * Ks[k0][d];
            s0 = a * 0.125f;
        }
        if (k1 <= r && k1 < T) {
            float a = 0.f;
#pragma unroll
            for (int d = 0; d < HD; d++) a += Qs[w][d] * Ks[k1][d];
            s1 = a * 0.125f;
        }
        float m = fmaxf(s0, s1);
#pragma unroll
        for (int o = 16; o; o >>= 1) m = fmaxf(m, __shfl_xor_sync(0xffffffffu, m, o));
        float e0 = (k0 <= r) ? __expf(s0 - m) : 0.f;
        float e1 = (k1 <= r && k1 < T) ? __expf(s1 - m) : 0.f;
        float ssum = e0 + e1;
#pragma unroll
        for (int o = 16; o; o >>= 1) ssum += __shfl_xor_sync(0xffffffffu, ssum, o);
        float inv = 1.f / ssum;
        Ps[w][k0] = e0 * inv;
        if (k1 < T) Ps[w][k1] = e1 * inv;
        __syncwarp();
        float a0 = 0.f, a1 = 0.f;
        for (int k = 0; k <= r; k++) {
            float p = Ps[w][k];
            a0 += p * Vs[k][lane];
            a1 += p * Vs[k][lane + 32];
        }
        size_t ob = ((size_t)(b * T + r)) * D + h * HD;
        ctxh[ob + lane] = __float2half_rn(a0);
        ctxh[ob + lane + 32] = __float2half_rn(a1);
        __syncwarp();
    }
}

// ---------------- u (scaled by 0.5) + c0 ----------------
__global__ void __launch_bounds__(256) u_kernel(const int* __restrict__ tokens,
                                                const float* __restrict__ cls_w,
                                                const float* __restrict__ cls_b,
                                                const float* __restrict__ fw2,
                                                const float* __restrict__ fb2,
                                                float* __restrict__ u,
                                                float* __restrict__ c0) {
    int bt0 = blockIdx.x * 8;
    int tid = threadIdx.x, w = tid >> 5, lane = tid & 31;
    __shared__ float ws[8][D];
    __shared__ int toksh[8];
    if (tid < 8) toksh[tid] = tokens[bt0 + tid];
    __syncthreads();
#pragma unroll
    for (int j = 0; j < 8; j++) ws[j][tid] = cls_w[(size_t)toksh[j] * D + tid];
    __syncthreads();
    {
        float s = 0.f;
        for (int d = lane; d < D; d += 32) s += fb2[d] * ws[w][d];
#pragma unroll
        for (int o = 16; o; o >>= 1) s += __shfl_xor_sync(0xffffffffu, s, o);
        if (!lane) c0[bt0 + w] = s + cls_b[toksh[w]];
    }
    float acc[8] = {};
    for (int d = 0; d < D; d++) {
        float f = fw2[(size_t)d * D + tid];
#pragma unroll
        for (int j = 0; j < 8; j++) acc[j] += ws[j][d] * f;
    }
#pragma unroll
    for (int j = 0; j < 8; j++) u[(size_t)(bt0 + j) * D + tid] = 0.5f * acc[j];
}

// ---------------- final: half2 gelu-dot + sigmoid (vectorized LDS) ----------------
constexpr int PT = 64;
constexpr int TT = 20;
constexpr int PROW = 132;
constexpr int SMEM_FINAL = (PT * PROW + TT * 128 * 2 + TT) * 4;  // 54,352 B

__global__ void __launch_bounds__(512, 2) final_kernel(const float* __restrict__ pproj,
                                                       const float* __restrict__ cproj,
                                                       const float* __restrict__ u,
                                                       const float* __restrict__ c0,
                                                       float* __restrict__ out) {
    extern __shared__ char smb[];
    cudaGridDependencySynchronize();
    __half2* pps = reinterpret_cast<__half2*>(smb);          // [PT][PROW] (p-major)
    __half2* cps = pps + PT * PROW;                          // [TT][128]
    __half2* us = cps + TT * 128;                            // [TT][128]
    float* c0s = reinterpret_cast<float*>(us + TT * 128);    // [TT]
    int b = blockIdx.x;
    int p0 = blockIdx.y * PT;
    int tb0 = blockIdx.z * TT;
    int tid = threadIdx.x;

    for (int i = tid; i < PT * (D / 2); i += 512) {
        int p = i >> 7;
        int e2 = i & 127;
        float2 v = *reinterpret_cast<const float2*>(&pproj[((size_t)(b * P + p0 + p)) * D + e2 * 2]);
        pps[p * PROW + e2] = __floats2half2_rn(v.x, v.y);
    }
    for (int i = tid; i < TT * (D / 2); i += 512) {
        int t = i >> 7;
        int e2 = i & 127;
        float2 cv = *reinterpret_cast<const float2*>(&cproj[((size_t)(b * T + tb0 + t)) * D + e2 * 2]);
        cps[t * 128 + e2] = __floats2half2_rn(cv.x, cv.y);
        float2 uv = *reinterpret_cast<const float2*>(&u[((size_t)(b * T + tb0 + t)) * D + e2 * 2]);
        us[t * 128 + e2] = __floats2half2_rn(uv.x, uv.y);
    }
    if (tid < TT) c0s[tid] = c0[b * T + tb0 + tid];
    __syncthreads();

    const __half2 C1 = __float2half2_rn(0.035677408f);
    const __half2 C2 = __float2half2_rn(0.7978845608f);
    const __half2 HZ = __float2half2_rn(0.f);

    int pl = tid & 63;
    int tg = tid >> 6;
    const int nt = (tg < TT - 16) ? 3 : 2;
    float acc[3] = {};
    __half2 hacc[3] = {HZ, HZ, HZ};
    const float4* perow = reinterpret_cast<const float4*>(pps + pl * PROW);

    for (int e4 = 0; e4 < 32; e4++) {
        float4 pef = perow[e4];
        const __half2* pe = reinterpret_cast<const __half2*>(&pef);
#pragma unroll 3
        for (int i = 0; i < 3; i++) {
            if (i < nt) {
                int t = tg + 8 * i;
                float4 cpf = *reinterpret_cast<const float4*>(cps + t * 128 + e4 * 4);
                float4 uuf = *reinterpret_cast<const float4*>(us + t * 128 + e4 * 4);
                const __half2* cp = reinterpret_cast<const __half2*>(&cpf);
                const __half2* uu = reinterpret_cast<const __half2*>(&uuf);
#pragma unroll
                for (int j = 0; j < 4; j++) {
                    __half2 x2 = __hadd2(pe[j], cp[j]);
                    __half2 sq = __hmul2(x2, x2);
                    __half2 t1 = __hfma2(C1, sq, C2);
                    __half2 th = htanh2(__hmul2(x2, t1));
                    __half2 w = __hmul2(x2, uu[j]);    // uu = 0.5*u
                    hacc[i] = __hadd2(hacc[i], __hfma2(w, th, w));
                }
            }
        }
        if ((e4 & 3) == 3) {
#pragma unroll 3
            for (int i = 0; i < 3; i++) {
                if (i < nt) {
                    float2 f = __half22float2(hacc[i]);
                    acc[i] += f.x + f.y;
                    hacc[i] = HZ;
                }
            }
        }
    }
    int p = p0 + pl;
#pragma unroll 3
    for (int i = 0; i < 3; i++) {
        if (i < nt) {
            int t = tg + 8 * i;
            float logit = acc[i] + c0s[t];
            out[((size_t)(b * P + p)) * T + tb0 + t] = 1.f / (1.f + __expf(-logit));
        }
    }
}

// ---------------- PDL launch helper ----------------
template <typename F, typename... AA>
static inline void launch_pdl(F k, dim3 g, dim3 b, size_t smem, AA... args) {
    cudaLaunchConfig_t cfg = {};
    cfg.gridDim = g;
    cfg.blockDim = b;
    cfg.dynamicSmemBytes = smem;
    cfg.stream = 0;
    cudaLaunchAttribute at[1];
    at[0].id = cudaLaunchAttributeProgrammaticStreamSerialization;
    at[0].val.programmaticStreamSerializationAllowed = 1;
    cfg.attrs = at;
    cfg.numAttrs = 1;
    cudaLaunchKernelEx(&cfg, k, args...);
}

// ---------------- host ----------------
extern "C" void kernel_launch(void* const* d_in, const int* in_sizes, int n_in,
                              void* d_out, int out_size) {
    const float* patches = (const float*)d_in[0];
    const int* tokens = (const int*)d_in[1];
    const float* tok_emb = (const float*)d_in[2];
    const float* pos_emb = (const float*)d_in[3];
    const float* qkv_w = (const float*)d_in[4];
    const float* qkv_b = (const float*)d_in[5];
    const float* out_w = (const float*)d_in[6];
    const float* out_b = (const float*)d_in[7];
    const float* ln1_s = (const float*)d_in[8];
    const float* ln1_b = (const float*)d_in[9];
    const float* w1 = (const float*)d_in[10];
    const float* b1 = (const float*)d_in[11];
    const float* w2 = (const float*)d_in[12];
    const float* b2 = (const float*)d_in[13];
    const float* ln2_s = (const float*)d_in[14];
    const float* ln2_b = (const float*)d_in[15];
    const float* fus_w1 = (const float*)d_in[16];
    const float* fus_b1 = (const float*)d_in[17];
    const float* fus_w2 = (const float*)d_in[18];
    const float* fus_b2 = (const float*)d_in[19];
    const float* cls_w = (const float*)d_in[20];
    const float* cls_b = (const float*)d_in[21];
    float* out = (float*)d_out;

    float *px, *py, *ppp, *pcp, *pu, *pc0;
    cudaGetSymbolAddress((void**)&px, g_x);
    cudaGetSymbolAddress((void**)&py, g_y);
    cudaGetSymbolAddress((void**)&ppp, g_pproj);
    cudaGetSymbolAddress((void**)&pcp, g_cproj);
    cudaGetSymbolAddress((void**)&pu, g_u);
    cudaGetSymbolAddress((void**)&pc0, g_c0);

    __half *pxh, *pqkvh, *pch, *phh, *pph, *pqwh, *powh, *pw1h, *pw2h, *pfwh;
    cudaGetSymbolAddress((void**)&pxh, g_xh);
    cudaGetSymbolAddress((void**)&pqkvh, g_qkvh);
    cudaGetSymbolAddress((void**)&pch, g_ctxh);
    cudaGetSymbolAddress((void**)&phh, g_hh);
    cudaGetSymbolAddress((void**)&pph, g_ph);
    cudaGetSymbolAddress((void**)&pqwh, g_qkvwh);
    cudaGetSymbolAddress((void**)&powh, g_outwh);
    cudaGetSymbolAddress((void**)&pw1h, g_w1h);
    cudaGetSymbolAddress((void**)&pw2h, g_w2h);
    cudaGetSymbolAddress((void**)&pfwh, g_fw1h);

    // instantiation aliases
    auto kQKV   = gemm_fp16<true, false, false, false, true, false, false>;   // A=pxh (L0)
    auto kOUT   = gemm_fp16<true, true, false, true, false, false, false>;    // outproj / ffn2
    auto kPPROJ = gemm_fp16<false, false, false, true, false, false, false>;
    auto kFFN1  = gemm_fp16<true, false, true, false, true, false, true>;     // LNSTAGE+RELU
    auto kQKVLN = gemm_fp16<true, false, false, false, true, false, true>;    // LNSTAGE (qkv L1)
    auto kCPROJ = gemm_fp16<true, false, false, true, false, true, true>;     // LNSTAGE+SHIFT

    cudaFuncSetAttribute(final_kernel, cudaFuncAttributeMaxDynamicSharedMemorySize, SMEM_FINAL);
    cudaFuncSetAttribute(kQKV, cudaFuncAttributeMaxDynamicSharedMemorySize, GEMM_SMEM);
    cudaFuncSetAttribute(kOUT, cudaFuncAttributeMaxDynamicSharedMemorySize, GEMM_SMEM);
    cudaFuncSetAttribute(kPPROJ, cudaFuncAttributeMaxDynamicSharedMemorySize, GEMM_SMEM);
    cudaFuncSetAttribute(kFFN1, cudaFuncAttributeMaxDynamicSharedMemorySize, GEMM_SMEM_LN);
    cudaFuncSetAttribute(kQKVLN, cudaFuncAttributeMaxDynamicSharedMemorySize, GEMM_SMEM_LN);
    cudaFuncSetAttribute(kCPROJ, cudaFuncAttributeMaxDynamicSharedMemorySize, GEMM_SMEM_LN);

    static cudaStream_t s1 = nullptr, s2 = nullptr;
    static cudaEvent_t ev0 = nullptr, ev1 = nullptr, ev2 = nullptr, ev3 = nullptr;
    if (!s1) {
        cudaStreamCreateWithFlags(&s1, cudaStreamNonBlocking);
        cudaStreamCreateWithFlags(&s2, cudaStreamNonBlocking);
        cudaEventCreateWithFlags(&ev0, cudaEventDisableTiming);
        cudaEventCreateWithFlags(&ev1, cudaEventDisableTiming);
        cudaEventCreateWithFlags(&ev2, cudaEventDisableTiming);
        cudaEventCreateWithFlags(&ev3, cudaEventDisableTiming);
    }

    // fork point BEFORE prep_main (side branches independent of it)
    cudaEventRecord(ev0, 0);
    cudaStreamWaitEvent(s1, ev0, 0);
    cudaStreamWaitEvent(s2, ev0, 0);

    // launch 1: prep_main (embed + L0 qkv w + out_w both layers)
    prep_main_kernel<<<512, 256>>>(qkv_w, out_w, tokens, tok_emb, pos_emb);

    // launches 2-4: qkv0, attn0, outproj0 (outproj = 4th submitted -> ncu target)
    launch_pdl(kQKV, dim3(3 * D / BN, M_ENC / BM), dim3(256), (size_t)GEMM_SMEM,
               (const __half*)pxh, (int)D,
               (const float*)nullptr, (const float*)nullptr, (const float*)nullptr, (float*)nullptr,
               (const __half*)pqwh, (int)D,
               (const float*)qkv_b, (const float*)nullptr,
               (float*)nullptr, (__half*)pqkvh, (int)(3 * D), (int)D);
    launch_pdl(attn_kernel, dim3(B * H), dim3(256), (size_t)0,
               (const __half*)pqkvh, (__half*)pch);
    launch_pdl(kOUT, dim3(D / BN, M_ENC / BM), dim3(256), (size_t)GEMM_SMEM,
               (const __half*)pch, (int)D,
               (const float*)nullptr, (const float*)nullptr, (const float*)nullptr, (float*)nullptr,
               (const __half*)powh, (int)D,
               (const float*)out_b, (const float*)px,
               (float*)py, (__half*)nullptr, (int)D, (int)D);

    // side branches (execute from t=0, concurrent with main chain)
    prep_fus_kernel<<<1024, 256, 0, s1>>>(fus_w1, patches);
    gemm_fp16<false, false, false, true, false, false, false><<<dim3(D / BN, B * P / BM), 256, GEMM_SMEM, s1>>>(
        pph, DINO, nullptr, nullptr, nullptr, nullptr,
        pfwh, DINO + D, nullptr, nullptr, ppp, nullptr, D, DINO);
    cudaEventRecord(ev1, s1);

    prep_rest_kernel<<<1024, 256, 0, s2>>>(qkv_w, w1, w2);
    cudaEventRecord(ev3, s2);
    u_kernel<<<M_ENC / 8, 256, 0, s2>>>(tokens, cls_w, cls_b, fus_w2, fus_b2, pu, pc0);
    cudaEventRecord(ev2, s2);

    // ffn1 l0 needs w1h from s2
    cudaStreamWaitEvent(0, ev3, 0);

    for (int l = 0; l < L; l++) {
        if (l > 0) {
            // qkv l1: LNSTAGE from py using ln2 params of layer l-1; writes px
            launch_pdl(kQKVLN, dim3(3 * D / BN, M_ENC / BM), dim3(256), (size_t)GEMM_SMEM_LN,
                       (const __half*)nullptr, (int)D,
                       (const float*)py, (const float*)(ln2_s + (size_t)(l - 1) * D),
                       (const float*)(ln2_b + (size_t)(l - 1) * D), (float*)px,
                       (const __half*)(pqwh + (size_t)l * 3 * D * D), (int)D,
                       (const float*)(qkv_b + (size_t)l * 3 * D), (const float*)nullptr,
                       (float*)nullptr, (__half*)pqkvh, (int)(3 * D), (int)D);
            launch_pdl(attn_kernel, dim3(B * H), dim3(256), (size_t)0,
                       (const __half*)pqkvh, (__half*)pch);
            launch_pdl(kOUT, dim3(D / BN, M_ENC / BM), dim3(256), (size_t)GEMM_SMEM,
                       (const __half*)pch, (int)D,
                       (const float*)nullptr, (const float*)nullptr, (const float*)nullptr, (float*)nullptr,
                       (const __half*)(powh + (size_t)l * D * D), (int)D,
                       (const float*)(out_b + (size_t)l * D), (const float*)px,
                       (float*)py, (__half*)nullptr, (int)D, (int)D);
        }
        // ffn1: LNSTAGE from py (ln1 params); writes px; relu fp16 out
        launch_pdl(kFFN1, dim3(DFF / BN, M_ENC / BM), dim3(256), (size_t)GEMM_SMEM_LN,
                   (const __half*)nullptr, (int)D,
                   (const float*)py, (const float*)(ln1_s + (size_t)l * D),
                   (const float*)(ln1_b + (size_t)l * D), (float*)px,
                   (const __half*)(pw1h + (size_t)l * DFF * D), (int)D,
                   (const float*)(b1 + (size_t)l * DFF), (const float*)nullptr,
                   (float*)nullptr, (__half*)phh, (int)DFF, (int)D);
        // ffn2 + residual(px)
        launch_pdl(kOUT, dim3(D / BN, M_ENC / BM), dim3(256), (size_t)GEMM_SMEM,
                   (const __half*)phh, (int)DFF,
                   (const float*)nullptr, (const float*)nullptr, (const float*)nullptr, (float*)nullptr,
                   (const __half*)(pw2h + (size_t)l * D * DFF), (int)DFF,
                   (const float*)(b2 + (size_t)l * D), (const float*)px,
                   (float*)py, (__half*)nullptr, (int)D, (int)DFF);
    }

    // cproj: LNSTAGE+SHIFT from py (ln2 params layer L-1)
    cudaStreamWaitEvent(0, ev1, 0);
    launch_pdl(kCPROJ, dim3(D / BN, M_ENC / BM), dim3(256), (size_t)GEMM_SMEM_LN,
               (const __half*)nullptr, (int)D,
               (const float*)py, (const float*)(ln2_s + (size_t)(L - 1) * D),
               (const float*)(ln2_b + (size_t)(L - 1) * D), (float*)nullptr,
               (const __half*)(pfwh + DINO), (int)(DINO + D),
               (const float*)fus_b1, (const float*)nullptr,
               (float*)pcp, (__half*)nullptr, (int)D, (int)D);

    cudaStreamWaitEvent(0, ev2, 0);
    launch_pdl(final_kernel, dim3(B, P / PT, T / TT), dim3(512), (size_t)SMEM_FINAL,
               (const float*)ppp, (const float*)pcp, (const float*)pu, (const float*)pc0,
               (float*)out);
}

// round 15
// speedup vs baseline: 1.4510x; 1.4510x over previous
#include <cuda_runtime.h>
#include <cuda_fp16.h>
#include <mma.h>
#include <stdint.h>

using namespace nvcuda;

// Model dims
constexpr int B = 32, T = 40, P = 256, V = 4096, D = 256, DINO = 384, H = 4, L = 2;
constexpr int HD = 64, DFF = 1024;
constexpr float EPS = 1e-5f;
constexpr int M_ENC = B * T;  // 1280

// ---------------- fp32 scratch ----------------
__device__ float g_x[M_ENC * D];
__device__ float g_y[M_ENC * D];
__device__ float g_pproj[B * P * D];
__device__ float g_cproj[M_ENC * D];
__device__ float g_u[M_ENC * D];
__device__ float g_c0[M_ENC];

// ---------------- fp16 scratch ----------------
__device__ __half g_xh[M_ENC * D];
__device__ __half g_qkvh[M_ENC * 3 * D];
__device__ __half g_ctxh[M_ENC * D];
__device__ __half g_hh[M_ENC * DFF];
__device__ __half g_ph[B * P * DINO];
__device__ __half g_qkvwh[L * 3 * D * D];
__device__ __half g_outwh[L * D * D];
__device__ __half g_w1h[L * DFF * D];
__device__ __half g_w2h[L * D * DFF];
__device__ __half g_fw1h[D * (DINO + D)];

// ---------------- helpers ----------------
__device__ __forceinline__ uint32_t smem_u32(const void* p) {
    uint32_t a;
    asm("{ .reg .u64 t; cvta.to.shared.u64 t, %1; cvt.u32.u64 %0, t; }" : "=r"(a) : "l"(p));
    return a;
}
__device__ __forceinline__ void cpa16(uint32_t dst, const void* src, int sz) {
    asm volatile("cp.async.cg.shared.global [%0], [%1], 16, %2;" :: "r"(dst), "l"(src), "r"(sz));
}
__device__ __forceinline__ void cpa_commit() { asm volatile("cp.async.commit_group;"); }

__device__ __forceinline__ __half2 htanh2(__half2 x) {
    uint32_t xi = *reinterpret_cast<uint32_t*>(&x);
    uint32_t ri;
    asm("tanh.approx.f16x2 %0, %1;" : "=r"(ri) : "r"(xi));
    return *reinterpret_cast<__half2*>(&ri);
}

__device__ __forceinline__ void cvt4(float4 v, __half* d, size_t off) {
    *reinterpret_cast<__half2*>(&d[off]) = __floats2half2_rn(v.x, v.y);
    *reinterpret_cast<__half2*>(&d[off + 2]) = __floats2half2_rn(v.z, v.w);
}

// ---------------- prep MAIN: embed + layer-0 qkv weights -> fp16 ----------------
__global__ void __launch_bounds__(256) prep_main_kernel(
    const float* __restrict__ qkv_w,
    const int* __restrict__ tokens, const float* __restrict__ tok_emb,
    const float* __restrict__ pos_emb) {
    constexpr int SQ0 = 3 * D * D / 4;
    constexpr int S7 = M_ENC * D / 4;
    constexpr int TOT = SQ0 + S7;
    for (int i = blockIdx.x * blockDim.x + threadIdx.x; i < TOT; i += gridDim.x * blockDim.x) {
        int j = i;
        if (j < SQ0) {
            float4 v = *reinterpret_cast<const float4*>(&qkv_w[(size_t)j * 4]);
            cvt4(v, g_qkvwh, (size_t)j * 4);
        } else {
            j -= SQ0;
            int bt = (j * 4) >> 8;
            int d0 = (j * 4) & 255;
            int t = bt % T;
            float4 te = *reinterpret_cast<const float4*>(&tok_emb[(size_t)tokens[bt] * D + d0]);
            float4 pe = *reinterpret_cast<const float4*>(&pos_emb[(size_t)t * D + d0]);
            float4 v = make_float4(te.x + pe.x, te.y + pe.y, te.z + pe.z, te.w + pe.w);
            *reinterpret_cast<float4*>(&g_x[(size_t)j * 4]) = v;
            cvt4(v, g_xh, (size_t)j * 4);
        }
    }
}

// ---------------- prep REST: remaining encoder weights -> fp16 (side stream) --------
__global__ void __launch_bounds__(256) prep_rest_kernel(
    const float* __restrict__ qkv_w, const float* __restrict__ out_w,
    const float* __restrict__ w1, const float* __restrict__ w2) {
    constexpr int SQ1 = 3 * D * D / 4;
    constexpr int S2 = L * D * D / 4;
    constexpr int S3 = L * DFF * D / 4;
    constexpr int S4 = L * D * DFF / 4;
    constexpr int TOT = SQ1 + S2 + S3 + S4;
    for (int i = blockIdx.x * blockDim.x + threadIdx.x; i < TOT; i += gridDim.x * blockDim.x) {
        int j = i;
        const float* src;
        __half* dh;
        size_t base = 0;
        if (j < SQ1) { src = qkv_w; dh = g_qkvwh; base = (size_t)SQ1 * 4; }
        else if ((j -= SQ1) < S2) { src = out_w; dh = g_outwh; }
        else if ((j -= S2) < S3) { src = w1; dh = g_w1h; }
        else { j -= S3; src = w2; dh = g_w2h; }
        float4 v = *reinterpret_cast<const float4*>(&src[base + (size_t)j * 4]);
        cvt4(v, dh, base + (size_t)j * 4);
    }
}

// ---------------- prep B: fusion weights + patches -> fp16 ----------------
__global__ void __launch_bounds__(256) prep_fus_kernel(
    const float* __restrict__ fus_w1, const float* __restrict__ patches) {
    constexpr int S5 = D * (DINO + D) / 4;
    constexpr int S6 = B * P * DINO / 4;
    constexpr int TOT = S5 + S6;
    for (int i = blockIdx.x * blockDim.x + threadIdx.x; i < TOT; i += gridDim.x * blockDim.x) {
        int j = i;
        const float* src;
        __half* dh;
        if (j < S5) { src = fus_w1; dh = g_fw1h; }
        else { j -= S5; src = patches; dh = g_ph; }
        float4 v = *reinterpret_cast<const float4*>(&src[(size_t)j * 4]);
        cvt4(v, dh, (size_t)j * 4);
    }
}

// ======================= fp16 single-pass GEMM, cp.async 3-stage =======================
constexpr int BM = 64, BN = 64, BK = 64;
constexpr int LDTE = 72;                  // halfs per smem row
constexpr int TILEB = 64 * LDTE * 2;      // 9216 B per tile
constexpr int NSTAGE = 3;
constexpr int GEMM_SMEM = NSTAGE * 2 * TILEB;  // 55296 B -> 3 CTAs/SM

template <bool BIAS, bool RES, bool RELU, bool EMIT32, bool EMITH, bool SHIFT>
__global__ void __launch_bounds__(256, 3) gemm_fp16(
    const __half* __restrict__ A, int lda,
    const __half* __restrict__ W, int ldw,
    const float* __restrict__ bias, const float* __restrict__ res,
    float* __restrict__ C32, __half* __restrict__ Ch,
    int ldc, int K) {
    extern __shared__ char sm[];
    cudaGridDependencySynchronize();   // PDL: wait for producer grid
    const int tid = threadIdx.x;
    const int n0 = blockIdx.x * BN;
    const int m0 = blockIdx.y * BM;
    const int nchunk = K / BK;
    const uint32_t sb0 = smem_u32(sm);

    auto stage = [&](int c) {
        const int buf = c % NSTAGE;
        const uint32_t sbase = sb0 + buf * 2 * TILEB;
        const int k0 = c * BK;
#pragma unroll
        for (int g = 0; g < 2; g++) {
            int gi = tid + g * 256;
            int row = gi >> 3, c16 = gi & 7;
            uint32_t soff = row * 144 + c16 * 16;
            int am = m0 + row;
            size_t aoff;
            int sz = 16;
            if (SHIFT) {
                int t = am % T;
                if (t == 0) { sz = 0; aoff = (size_t)am * lda + k0 + c16 * 8; }
                else aoff = (size_t)(am - 1) * lda + k0 + c16 * 8;
            } else {
                aoff = (size_t)am * lda + k0 + c16 * 8;
            }
            cpa16(sbase + soff, A + aoff, sz);
            size_t woff = (size_t)(n0 + row) * ldw + k0 + c16 * 8;
            cpa16(sbase + TILEB + soff, W + woff, 16);
        }
        cpa_commit();
    };

    stage(0);
    if (nchunk > 1) stage(1);

    const int w = tid >> 5;
    const int wm = w >> 2;
    const int wn = w & 3;

    wmma::fragment<wmma::accumulator, 16, 16, 16, float> acc[2];
    wmma::fill_fragment(acc[0], 0.f);
    wmma::fill_fragment(acc[1], 0.f);

    for (int c = 0; c < nchunk; c++) {
        if (c + 1 < nchunk) {
            asm volatile("cp.async.wait_group 1;");
        } else {
            asm volatile("cp.async.wait_group 0;");
        }
        __syncthreads();      // chunk c visible; prior compute on buf (c+2)%3 done
        if (c + 2 < nchunk) stage(c + 2);   // issue loads BEFORE compute (3rd buffer free)
        char* bb = sm + (c % NSTAGE) * 2 * TILEB;
        const __half* tA = reinterpret_cast<const __half*>(bb);
        const __half* tW = reinterpret_cast<const __half*>(bb + TILEB);
#pragma unroll
        for (int ks = 0; ks < 4; ks++) {
            wmma::fragment<wmma::matrix_b, 16, 16, 16, __half, wmma::col_major> bh;
            wmma::load_matrix_sync(bh, &tW[(wn * 16) * LDTE + ks * 16], LDTE);
            wmma::fragment<wmma::matrix_a, 16, 16, 16, __half, wmma::row_major> ah[2];
            wmma::load_matrix_sync(ah[0], &tA[(wm * 32) * LDTE + ks * 16], LDTE);
            wmma::load_matrix_sync(ah[1], &tA[(wm * 32 + 16) * LDTE + ks * 16], LDTE);
            wmma::mma_sync(acc[0], ah[0], bh, acc[0]);
            wmma::mma_sync(acc[1], ah[1], bh, acc[1]);
        }
    }
    __syncthreads();   // all warps done before epilogue aliases smem

    float* Cs = reinterpret_cast<float*>(sm);
    wmma::store_matrix_sync(&Cs[(wm * 32) * LDTE + wn * 16], acc[0], LDTE, wmma::mem_row_major);
    wmma::store_matrix_sync(&Cs[(wm * 32 + 16) * LDTE + wn * 16], acc[1], LDTE, wmma::mem_row_major);
    __syncthreads();

#pragma unroll
    for (int i = tid * 4; i < BM * BN; i += 1024) {
        int r = i >> 6, cc = i & 63;
        int m = m0 + r, n = n0 + cc;
        float4 v = *reinterpret_cast<const float4*>(&Cs[r * LDTE + cc]);
        if (BIAS) {
            float4 bv = *reinterpret_cast<const float4*>(&bias[n]);
            v.x += bv.x; v.y += bv.y; v.z += bv.z; v.w += bv.w;
        }
        if (RES) {
            float4 rv = *reinterpret_cast<const float4*>(&res[(size_t)m * ldc + n]);
            v.x += rv.x; v.y += rv.y; v.z += rv.z; v.w += rv.w;
        }
        if (RELU) {
            v.x = fmaxf(v.x, 0.f); v.y = fmaxf(v.y, 0.f);
            v.z = fmaxf(v.z, 0.f); v.w = fmaxf(v.w, 0.f);
        }
        if (EMIT32) *reinterpret_cast<float4*>(&C32[(size_t)m * ldc + n]) = v;
        if (EMITH) {
            *reinterpret_cast<__half2*>(&Ch[(size_t)m * ldc + n]) = __floats2half2_rn(v.x, v.y);
            *reinterpret_cast<__half2*>(&Ch[(size_t)m * ldc + n + 2]) = __floats2half2_rn(v.z, v.w);
        }
    }
}

// ---------------- attention (fp16 qkv in, fp16 ctx out) ----------------
__global__ void __launch_bounds__(256) attn_kernel(const __half* __restrict__ qkv,
                                                   __half* __restrict__ ctxh) {
    cudaGridDependencySynchronize();
    int bh = blockIdx.x;
    int b = bh / H;
    int h = bh % H;
    __shared__ float Ks[T][HD + 1];
    __shared__ float Vs[T][HD + 1];
    __shared__ float Qs[8][HD];
    __shared__ float Ps[8][T];
    int tid = threadIdx.x;
    int w = tid >> 5, lane = tid & 31;
    for (int i = tid; i < T * HD; i += 256) {
        int t = i >> 6, d = i & 63;
        size_t base = ((size_t)(b * T + t)) * (3 * D) + h * HD + d;
        Ks[t][d] = __half2float(qkv[base + D]);
        Vs[t][d] = __half2float(qkv[base + 2 * D]);
    }
    __syncthreads();
    for (int r = w; r < T; r += 8) {
        size_t qb = ((size_t)(b * T + r)) * (3 * D) + h * HD;
        Qs[w][lane] = __half2float(qkv[qb + lane]);
        Qs[w][lane + 32] = __half2float(qkv[qb + lane + 32]);
        __syncwarp();
        int k0 = lane, k1 = lane + 32;
        float s0 = -1e30f, s1 = -1e30f;
        if (k0 <= r) {
            float a = 0.f;
#pragma unroll
            for (int d = 0; d < HD; d++) a += Qs[w][d] * Ks[k0][d];
            s0 = a * 0.125f;
        }
        if (k1 <= r && k1 < T) {
            float a = 0.f;
#pragma unroll
            for (int d = 0; d < HD; d++) a += Qs[w][d] * Ks[k1][d];
            s1 = a * 0.125f;
        }
        float m = fmaxf(s0, s1);
#pragma unroll
        for (int o = 16; o; o >>= 1) m = fmaxf(m, __shfl_xor_sync(0xffffffffu, m, o));
        float e0 = (k0 <= r) ? __expf(s0 - m) : 0.f;
        float e1 = (k1 <= r && k1 < T) ? __expf(s1 - m) : 0.f;
        float ssum = e0 + e1;
#pragma unroll
        for (int o = 16; o; o >>= 1) ssum += __shfl_xor_sync(0xffffffffu, ssum, o);
        float inv = 1.f / ssum;
        Ps[w][k0] = e0 * inv;
        if (k1 < T) Ps[w][k1] = e1 * inv;
        __syncwarp();
        float a0 = 0.f, a1 = 0.f;
        for (int k = 0; k <= r; k++) {
            float p = Ps[w][k];
            a0 += p * Vs[k][lane];
            a1 += p * Vs[k][lane + 32];
        }
        size_t ob = ((size_t)(b * T + r)) * D + h * HD;
        ctxh[ob + lane] = __float2half_rn(a0);
        ctxh[ob + lane + 32] = __float2half_rn(a1);
        __syncwarp();
    }
}

// ---------------- layernorm ----------------
__global__ void __launch_bounds__(256) ln_kernel(const float* __restrict__ in,
                                                 const float* __restrict__ sc,
                                                 const float* __restrict__ bi,
                                                 float* __restrict__ out32,
                                                 __half* __restrict__ outh) {
    cudaGridDependencySynchronize();
    int row = blockIdx.x, tid = threadIdx.x;
    float v = in[(size_t)row * D + tid];
    float sum = v, sq = v * v;
#pragma unroll
    for (int o = 16; o; o >>= 1) {
        sum += __shfl_xor_sync(0xffffffffu, sum, o);
        sq += __shfl_xor_sync(0xffffffffu, sq, o);
    }
    __shared__ float r1[8], r2[8];
    int w = tid >> 5, lane = tid & 31;
    if (!lane) { r1[w] = sum; r2[w] = sq; }
    __syncthreads();
    if (w == 0) {
        float a = (lane < 8) ? r1[lane] : 0.f;
        float b2 = (lane < 8) ? r2[lane] : 0.f;
#pragma unroll
        for (int o = 4; o; o >>= 1) {
            a += __shfl_xor_sync(0xffffffffu, a, o);
            b2 += __shfl_xor_sync(0xffffffffu, b2, o);
        }
        if (!lane) { r1[0] = a; r2[0] = b2; }
    }
    __syncthreads();
    float mean = r1[0] * (1.f / 256.f);
    float var = r2[0] * (1.f / 256.f) - mean * mean;
    float o = (v - mean) * rsqrtf(var + EPS) * sc[tid] + bi[tid];
    size_t idx = (size_t)row * D + tid;
    out32[idx] = o;
    outh[idx] = __float2half_rn(o);
}

// ---------------- u (scaled by 0.5) + c0 ----------------
__global__ void __launch_bounds__(256) u_kernel(const int* __restrict__ tokens,
                                                const float* __restrict__ cls_w,
                                                const float* __restrict__ cls_b,
                                                const float* __restrict__ fw2,
                                                const float* __restrict__ fb2,
                                                float* __restrict__ u,
                                                float* __restrict__ c0) {
    int bt0 = blockIdx.x * 8;
    int tid = threadIdx.x, w = tid >> 5, lane = tid & 31;
    __shared__ float ws[8][D];
    __shared__ int toksh[8];
    if (tid < 8) toksh[tid] = tokens[bt0 + tid];
    __syncthreads();
#pragma unroll
    for (int j = 0; j < 8; j++) ws[j][tid] = cls_w[(size_t)toksh[j] * D + tid];
    __syncthreads();
    {
        float s = 0.f;
        for (int d = lane; d < D; d += 32) s += fb2[d] * ws[w][d];
#pragma unroll
        for (int o = 16; o; o >>= 1) s += __shfl_xor_sync(0xffffffffu, s, o);
        if (!lane) c0[bt0 + w] = s + cls_b[toksh[w]];
    }
    float acc[8] = {};
    for (int d = 0; d < D; d++) {
        float f = fw2[(size_t)d * D + tid];
#pragma unroll
        for (int j = 0; j < 8; j++) acc[j] += ws[j][d] * f;
    }
#pragma unroll
    for (int j = 0; j < 8; j++) u[(size_t)(bt0 + j) * D + tid] = 0.5f * acc[j];
}

// ---------------- final: half2 gelu-dot + sigmoid (vectorized LDS) ----------------
constexpr int PT = 64;
constexpr int TT = 20;
constexpr int PROW = 132;
constexpr int SMEM_FINAL = (PT * PROW + TT * 128 * 2 + TT) * 4;  // 54,352 B

__global__ void __launch_bounds__(512, 2) final_kernel(const float* __restrict__ pproj,
                                                       const float* __restrict__ cproj,
                                                       const float* __restrict__ u,
                                                       const float* __restrict__ c0,
                                                       float* __restrict__ out) {
    extern __shared__ char smb[];
    cudaGridDependencySynchronize();
    __half2* pps = reinterpret_cast<__half2*>(smb);          // [PT][PROW] (p-major)
    __half2* cps = pps + PT * PROW;                          // [TT][128]
    __half2* us = cps + TT * 128;                            // [TT][128]
    float* c0s = reinterpret_cast<float*>(us + TT * 128);    // [TT]
    int b = blockIdx.x;
    int p0 = blockIdx.y * PT;
    int tb0 = blockIdx.z * TT;
    int tid = threadIdx.x;

    for (int i = tid; i < PT * (D / 2); i += 512) {
        int p = i >> 7;
        int e2 = i & 127;
        float2 v = *reinterpret_cast<const float2*>(&pproj[((size_t)(b * P + p0 + p)) * D + e2 * 2]);
        pps[p * PROW + e2] = __floats2half2_rn(v.x, v.y);
    }
    for (int i = tid; i < TT * (D / 2); i += 512) {
        int t = i >> 7;
        int e2 = i & 127;
        float2 cv = *reinterpret_cast<const float2*>(&cproj[((size_t)(b * T + tb0 + t)) * D + e2 * 2]);
        cps[t * 128 + e2] = __floats2half2_rn(cv.x, cv.y);
        float2 uv = *reinterpret_cast<const float2*>(&u[((size_t)(b * T + tb0 + t)) * D + e2 * 2]);
        us[t * 128 + e2] = __floats2half2_rn(uv.x, uv.y);
    }
    if (tid < TT) c0s[tid] = c0[b * T + tb0 + tid];
    __syncthreads();

    const __half2 C1 = __float2half2_rn(0.035677408f);
    const __half2 C2 = __float2half2_rn(0.7978845608f);
    const __half2 HZ = __float2half2_rn(0.f);

    int pl = tid & 63;
    int tg = tid >> 6;
    const int nt = (tg < TT - 16) ? 3 : 2;
    float acc[3] = {};
    __half2 hacc[3] = {HZ, HZ, HZ};
    const float4* perow = reinterpret_cast<const float4*>(pps + pl * PROW);

    for (int e4 = 0; e4 < 32; e4++) {
        float4 pef = perow[e4];
        const __half2* pe = reinterpret_cast<const __half2*>(&pef);
#pragma unroll 3
        for (int i = 0; i < 3; i++) {
            if (i < nt) {
                int t = tg + 8 * i;
                float4 cpf = *reinterpret_cast<const float4*>(cps + t * 128 + e4 * 4);
                float4 uuf = *reinterpret_cast<const float4*>(us + t * 128 + e4 * 4);
                const __half2* cp = reinterpret_cast<const __half2*>(&cpf);
                const __half2* uu = reinterpret_cast<const __half2*>(&uuf);
#pragma unroll
                for (int j = 0; j < 4; j++) {
                    __half2 x2 = __hadd2(pe[j], cp[j]);
                    __half2 sq = __hmul2(x2, x2);
                    __half2 t1 = __hfma2(C1, sq, C2);
                    __half2 th = htanh2(__hmul2(x2, t1));
                    __half2 w = __hmul2(x2, uu[j]);    // uu = 0.5*u
                    hacc[i] = __hadd2(hacc[i], __hfma2(w, th, w));
                }
            }
        }
        if ((e4 & 3) == 3) {
#pragma unroll 3
            for (int i = 0; i < 3; i++) {
                if (i < nt) {
                    float2 f = __half22float2(hacc[i]);
                    acc[i] += f.x + f.y;
                    hacc[i] = HZ;
                }
            }
        }
    }
    int p = p0 + pl;
#pragma unroll 3
    for (int i = 0; i < 3; i++) {
        if (i < nt) {
            int t = tg + 8 * i;
            float logit = acc[i] + c0s[t];
            out[((size_t)(b * P + p)) * T + tb0 + t] = 1.f / (1.f + __expf(-logit));
        }
    }
}

// ---------------- PDL launch helper ----------------
template <typename F, typename... AA>
static inline void launch_pdl(F k, dim3 g, dim3 b, size_t smem, AA... args) {
    cudaLaunchConfig_t cfg = {};
    cfg.gridDim = g;
    cfg.blockDim = b;
    cfg.dynamicSmemBytes = smem;
    cfg.stream = 0;
    cudaLaunchAttribute at[1];
    at[0].id = cudaLaunchAttributeProgrammaticStreamSerialization;
    at[0].val.programmaticStreamSerializationAllowed = 1;
    cfg.attrs = at;
    cfg.numAttrs = 1;
    cudaLaunchKernelEx(&cfg, k, args...);
}

// ---------------- host ----------------
extern "C" void kernel_launch(void* const* d_in, const int* in_sizes, int n_in,
                              void* d_out, int out_size) {
    const float* patches = (const float*)d_in[0];
    const int* tokens = (const int*)d_in[1];
    const float* tok_emb = (const float*)d_in[2];
    const float* pos_emb = (const float*)d_in[3];
    const float* qkv_w = (const float*)d_in[4];
    const float* qkv_b = (const float*)d_in[5];
    const float* out_w = (const float*)d_in[6];
    const float* out_b = (const float*)d_in[7];
    const float* ln1_s = (const float*)d_in[8];
    const float* ln1_b = (const float*)d_in[9];
    const float* w1 = (const float*)d_in[10];
    const float* b1 = (const float*)d_in[11];
    const float* w2 = (const float*)d_in[12];
    const float* b2 = (const float*)d_in[13];
    const float* ln2_s = (const float*)d_in[14];
    const float* ln2_b = (const float*)d_in[15];
    const float* fus_w1 = (const float*)d_in[16];
    const float* fus_b1 = (const float*)d_in[17];
    const float* fus_w2 = (const float*)d_in[18];
    const float* fus_b2 = (const float*)d_in[19];
    const float* cls_w = (const float*)d_in[20];
    const float* cls_b = (const float*)d_in[21];
    float* out = (float*)d_out;

    float *px, *py, *ppp, *pcp, *pu, *pc0;
    cudaGetSymbolAddress((void**)&px, g_x);
    cudaGetSymbolAddress((void**)&py, g_y);
    cudaGetSymbolAddress((void**)&ppp, g_pproj);
    cudaGetSymbolAddress((void**)&pcp, g_cproj);
    cudaGetSymbolAddress((void**)&pu, g_u);
    cudaGetSymbolAddress((void**)&pc0, g_c0);

    __half *pxh, *pqkvh, *pch, *phh, *pph, *pqwh, *powh, *pw1h, *pw2h, *pfwh;
    cudaGetSymbolAddress((void**)&pxh, g_xh);
    cudaGetSymbolAddress((void**)&pqkvh, g_qkvh);
    cudaGetSymbolAddress((void**)&pch, g_ctxh);
    cudaGetSymbolAddress((void**)&phh, g_hh);
    cudaGetSymbolAddress((void**)&pph, g_ph);
    cudaGetSymbolAddress((void**)&pqwh, g_qkvwh);
    cudaGetSymbolAddress((void**)&powh, g_outwh);
    cudaGetSymbolAddress((void**)&pw1h, g_w1h);
    cudaGetSymbolAddress((void**)&pw2h, g_w2h);
    cudaGetSymbolAddress((void**)&pfwh, g_fw1h);

    cudaFuncSetAttribute(final_kernel, cudaFuncAttributeMaxDynamicSharedMemorySize, SMEM_FINAL);
    cudaFuncSetAttribute(gemm_fp16<true, false, false, false, true, false>, cudaFuncAttributeMaxDynamicSharedMemorySize, GEMM_SMEM);
    cudaFuncSetAttribute(gemm_fp16<true, true, false, true, false, false>, cudaFuncAttributeMaxDynamicSharedMemorySize, GEMM_SMEM);
    cudaFuncSetAttribute(gemm_fp16<true, false, true, false, true, false>, cudaFuncAttributeMaxDynamicSharedMemorySize, GEMM_SMEM);
    cudaFuncSetAttribute(gemm_fp16<false, false, false, true, false, false>, cudaFuncAttributeMaxDynamicSharedMemorySize, GEMM_SMEM);
    cudaFuncSetAttribute(gemm_fp16<true, false, false, true, false, true>, cudaFuncAttributeMaxDynamicSharedMemorySize, GEMM_SMEM);

    static cudaStream_t s1 = nullptr, s2 = nullptr;
    static cudaEvent_t ev0 = nullptr, ev1 = nullptr, ev2 = nullptr, ev3 = nullptr;
    if (!s1) {
        cudaStreamCreateWithFlags(&s1, cudaStreamNonBlocking);
        cudaStreamCreateWithFlags(&s2, cudaStreamNonBlocking);
        cudaEventCreateWithFlags(&ev0, cudaEventDisableTiming);
        cudaEventCreateWithFlags(&ev1, cudaEventDisableTiming);
        cudaEventCreateWithFlags(&ev2, cudaEventDisableTiming);
        cudaEventCreateWithFlags(&ev3, cudaEventDisableTiming);
    }

    // launch 1: prep_main (embed + L0 qkv weights)
    prep_main_kernel<<<512, 256>>>(qkv_w, tokens, tok_emb, pos_emb);

    // fork side branches
    cudaEventRecord(ev0, 0);
    cudaStreamWaitEvent(s1, ev0, 0);
    cudaStreamWaitEvent(s2, ev0, 0);

    // s1: fusion prep + pproj            (launches 2, 3)
    prep_fus_kernel<<<1024, 256, 0, s1>>>(fus_w1, patches);
    gemm_fp16<false, false, false, true, false, false><<<dim3(D / BN, B * P / BM), 256, GEMM_SMEM, s1>>>(
        pph, DINO, pfwh, DINO + D, nullptr, nullptr, ppp, nullptr, D, DINO);
    cudaEventRecord(ev1, s1);

    // launch 4: qkv GEMM layer 0; launch 5: attn layer 0
    launch_pdl(gemm_fp16<true, false, false, false, true, false>,
               dim3(3 * D / BN, M_ENC / BM), dim3(256), (size_t)GEMM_SMEM,
               (const __half*)pxh, (int)D, (const __half*)pqwh, (int)D,
               (const float*)qkv_b, (const float*)nullptr,
               (float*)nullptr, (__half*)pqkvh, (int)(3 * D), (int)D);
    launch_pdl(attn_kernel, dim3(B * H), dim3(256), (size_t)0,
               (const __half*)pqkvh, (__half*)pch);

    // s2: remaining encoder weights + u/c0 (runs concurrent with qkv/attn)
    prep_rest_kernel<<<1024, 256, 0, s2>>>(qkv_w, out_w, w1, w2);
    cudaEventRecord(ev3, s2);
    u_kernel<<<M_ENC / 8, 256, 0, s2>>>(tokens, cls_w, cls_b, fus_w2, fus_b2, pu, pc0);
    cudaEventRecord(ev2, s2);

    for (int l = 0; l < L; l++) {
        if (l > 0) {
            launch_pdl(gemm_fp16<true, false, false, false, true, false>,
                       dim3(3 * D / BN, M_ENC / BM), dim3(256), (size_t)GEMM_SMEM,
                       (const __half*)pxh, (int)D, (const __half*)(pqwh + (size_t)l * 3 * D * D), (int)D,
                       (const float*)(qkv_b + (size_t)l * 3 * D), (const float*)nullptr,
                       (float*)nullptr, (__half*)pqkvh, (int)(3 * D), (int)D);
            launch_pdl(attn_kernel, dim3(B * H), dim3(256), (size_t)0,
                       (const __half*)pqkvh, (__half*)pch);
        }
        if (l == 0) cudaStreamWaitEvent(0, ev3, 0);   // need out_w/w1/w2 fp16 from s2
        // outproj + residual
        launch_pdl(gemm_fp16<true, true, false, true, false, false>,
                   dim3(D / BN, M_ENC / BM), dim3(256), (size_t)GEMM_SMEM,
                   (const __half*)pch, (int)D, (const __half*)(powh + (size_t)l * D * D), (int)D,
                   (const float*)(out_b + (size_t)l * D), (const float*)px,
                   (float*)py, (__half*)nullptr, (int)D, (int)D);
        launch_pdl(ln_kernel, dim3(M_ENC), dim3(256), (size_t)0,
                   (const float*)py, (const float*)(ln1_s + (size_t)l * D), (const float*)(ln1_b + (size_t)l * D),
                   (float*)px, (__half*)pxh);
        // ffn1 (relu, fp16 out)
        launch_pdl(gemm_fp16<true, false, true, false, true, false>,
                   dim3(DFF / BN, M_ENC / BM), dim3(256), (size_t)GEMM_SMEM,
                   (const __half*)pxh, (int)D, (const __half*)(pw1h + (size_t)l * DFF * D), (int)D,
                   (const float*)(b1 + (size_t)l * DFF), (const float*)nullptr,
                   (float*)nullptr, (__half*)phh, (int)DFF, (int)D);
        // ffn2 + residual
        launch_pdl(gemm_fp16<true, true, false, true, false, false>,
                   dim3(D / BN, M_ENC / BM), dim3(256), (size_t)GEMM_SMEM,
                   (const __half*)phh, (int)DFF, (const __half*)(pw2h + (size_t)l * D * DFF), (int)DFF,
                   (const float*)(b2 + (size_t)l * D), (const float*)px,
                   (float*)py, (__half*)nullptr, (int)D, (int)DFF);
        launch_pdl(ln_kernel, dim3(M_ENC), dim3(256), (size_t)0,
                   (const float*)py, (const float*)(ln2_s + (size_t)l * D), (const float*)(ln2_b + (size_t)l * D),
                   (float*)px, (__half*)pxh);
    }

    // join: cproj (needs fus_w1 fp16 from s1); shift folded into staging
    cudaStreamWaitEvent(0, ev1, 0);
    launch_pdl(gemm_fp16<true, false, false, true, false, true>,
               dim3(D / BN, M_ENC / BM), dim3(256), (size_t)GEMM_SMEM,
               (const __half*)pxh, (int)D, (const __half*)(pfwh + DINO), (int)(DINO + D),
               (const float*)fus_b1, (const float*)nullptr,
               (float*)pcp, (__half*)nullptr, (int)D, (int)D);

    cudaStreamWaitEvent(0, ev2, 0);
    launch_pdl(final_kernel, dim3(B, P / PT, T / TT), dim3(512), (size_t)SMEM_FINAL,
               (const float*)ppp, (const float*)pcp, (const float*)pu, (const float*)pc0,
               (float*)out);
}

// round 16
// speedup vs baseline: 1.4777x; 1.0184x over previous
#include <cuda_runtime.h>
#include <cuda_fp16.h>
#include <mma.h>
#include <stdint.h>

using namespace nvcuda;

// Model dims
constexpr int B = 32, T = 40, P = 256, V = 4096, D = 256, DINO = 384, H = 4, L = 2;
constexpr int HD = 64, DFF = 1024;
constexpr float EPS = 1e-5f;
constexpr int M_ENC = B * T;  // 1280

// ---------------- fp32 scratch ----------------
__device__ float g_x[M_ENC * D];
__device__ float g_y[M_ENC * D];
__device__ float g_pproj[B * P * D];
__device__ float g_cproj[M_ENC * D];
__device__ float g_u[M_ENC * D];
__device__ float g_c0[M_ENC];

// ---------------- fp16 scratch ----------------
__device__ __half g_xh[M_ENC * D];
__device__ __half g_qkvh[M_ENC * 3 * D];
__device__ __half g_ctxh[M_ENC * D];
__device__ __half g_hh[M_ENC * DFF];
__device__ __half g_ph[B * P * DINO];
__device__ __half g_qkvwh[L * 3 * D * D];
__device__ __half g_outwh[L * D * D];
__device__ __half g_w1h[L * DFF * D];
__device__ __half g_w2h[L * D * DFF];
__device__ __half g_fw1h[D * (DINO + D)];

// ---------------- helpers ----------------
__device__ __forceinline__ uint32_t smem_u32(const void* p) {
    uint32_t a;
    asm("{ .reg .u64 t; cvta.to.shared.u64 t, %1; cvt.u32.u64 %0, t; }" : "=r"(a) : "l"(p));
    return a;
}
__device__ __forceinline__ void cpa16(uint32_t dst, const void* src, int sz) {
    asm volatile("cp.async.cg.shared.global [%0], [%1], 16, %2;" :: "r"(dst), "l"(src), "r"(sz));
}
__device__ __forceinline__ void cpa_commit() { asm volatile("cp.async.commit_group;"); }

__device__ __forceinline__ __half2 htanh2(__half2 x) {
    uint32_t xi = *reinterpret_cast<uint32_t*>(&x);
    uint32_t ri;
    asm("tanh.approx.f16x2 %0, %1;" : "=r"(ri) : "r"(xi));
    return *reinterpret_cast<__half2*>(&ri);
}

__device__ __forceinline__ void cvt4(float4 v, __half* d, size_t off) {
    *reinterpret_cast<__half2*>(&d[off]) = __floats2half2_rn(v.x, v.y);
    *reinterpret_cast<__half2*>(&d[off + 2]) = __floats2half2_rn(v.z, v.w);
}

// ---------------- prep MAIN: embed + layer-0 qkv weights -> fp16 ----------------
__global__ void __launch_bounds__(256) prep_main_kernel(
    const float* __restrict__ qkv_w,
    const int* __restrict__ tokens, const float* __restrict__ tok_emb,
    const float* __restrict__ pos_emb) {
    constexpr int SQ0 = 3 * D * D / 4;
    constexpr int S7 = M_ENC * D / 4;
    constexpr int TOT = SQ0 + S7;
    for (int i = blockIdx.x * blockDim.x + threadIdx.x; i < TOT; i += gridDim.x * blockDim.x) {
        int j = i;
        if (j < SQ0) {
            float4 v = *reinterpret_cast<const float4*>(&qkv_w[(size_t)j * 4]);
            cvt4(v, g_qkvwh, (size_t)j * 4);
        } else {
            j -= SQ0;
            int bt = (j * 4) >> 8;
            int d0 = (j * 4) & 255;
            int t = bt % T;
            float4 te = *reinterpret_cast<const float4*>(&tok_emb[(size_t)tokens[bt] * D + d0]);
            float4 pe = *reinterpret_cast<const float4*>(&pos_emb[(size_t)t * D + d0]);
            float4 v = make_float4(te.x + pe.x, te.y + pe.y, te.z + pe.z, te.w + pe.w);
            *reinterpret_cast<float4*>(&g_x[(size_t)j * 4]) = v;
            cvt4(v, g_xh, (size_t)j * 4);
        }
    }
}

// ---------------- prep REST: remaining encoder weights -> fp16 (side stream) --------
__global__ void __launch_bounds__(256) prep_rest_kernel(
    const float* __restrict__ qkv_w, const float* __restrict__ out_w,
    const float* __restrict__ w1, const float* __restrict__ w2) {
    constexpr int SQ1 = 3 * D * D / 4;
    constexpr int S2 = L * D * D / 4;
    constexpr int S3 = L * DFF * D / 4;
    constexpr int S4 = L * D * DFF / 4;
    constexpr int TOT = SQ1 + S2 + S3 + S4;
    for (int i = blockIdx.x * blockDim.x + threadIdx.x; i < TOT; i += gridDim.x * blockDim.x) {
        int j = i;
        const float* src;
        __half* dh;
        size_t base = 0;
        if (j < SQ1) { src = qkv_w; dh = g_qkvwh; base = (size_t)SQ1 * 4; }
        else if ((j -= SQ1) < S2) { src = out_w; dh = g_outwh; }
        else if ((j -= S2) < S3) { src = w1; dh = g_w1h; }
        else { j -= S3; src = w2; dh = g_w2h; }
        float4 v = *reinterpret_cast<const float4*>(&src[base + (size_t)j * 4]);
        cvt4(v, dh, base + (size_t)j * 4);
    }
}

// ---------------- prep B: fusion weights + patches -> fp16 ----------------
__global__ void __launch_bounds__(256) prep_fus_kernel(
    const float* __restrict__ fus_w1, const float* __restrict__ patches) {
    constexpr int S5 = D * (DINO + D) / 4;
    constexpr int S6 = B * P * DINO / 4;
    constexpr int TOT = S5 + S6;
    for (int i = blockIdx.x * blockDim.x + threadIdx.x; i < TOT; i += gridDim.x * blockDim.x) {
        int j = i;
        const float* src;
        __half* dh;
        if (j < S5) { src = fus_w1; dh = g_fw1h; }
        else { j -= S5; src = patches; dh = g_ph; }
        float4 v = *reinterpret_cast<const float4*>(&src[(size_t)j * 4]);
        cvt4(v, dh, (size_t)j * 4);
    }
}

// ======================= fp16 GEMM, 3-stage; W prefetched pre-gridsync (WPRE) ==========
// Commit order (WPRE):  W0, W1, [gridsync], A0, A1, then combined A+W groups in-loop.
// Commit order (!WPRE): [gridsync], AW0, AW1, then combined. wait_group 1 before chunk c
// retires all groups needed for chunk c in both schemes (groups retire in commit order).
constexpr int BM = 64, BN = 64, BK = 64;
constexpr int LDTE = 72;
constexpr int TILEB = 64 * LDTE * 2;      // 9216 B per tile
constexpr int NSTAGE = 3;
constexpr int GEMM_SMEM = NSTAGE * 2 * TILEB;  // 55296 B -> 3 CTAs/SM

template <bool BIAS, bool RES, bool RELU, bool EMIT32, bool EMITH, bool SHIFT, bool WPRE>
__global__ void __launch_bounds__(256, 3) gemm_fp16(
    const __half* __restrict__ A, int lda,
    const __half* __restrict__ W, int ldw,
    const float* __restrict__ bias, const float* __restrict__ res,
    float* __restrict__ C32, __half* __restrict__ Ch,
    int ldc, int K) {
    extern __shared__ char sm[];
    const int tid = threadIdx.x;
    const int n0 = blockIdx.x * BN;
    const int m0 = blockIdx.y * BM;
    const int nchunk = K / BK;
    const uint32_t sb0 = smem_u32(sm);

    auto stageW = [&](int c) {
        const uint32_t sbase = sb0 + (c % NSTAGE) * 2 * TILEB + TILEB;
        const int k0 = c * BK;
#pragma unroll
        for (int g = 0; g < 2; g++) {
            int gi = tid + g * 256;
            int row = gi >> 3, c16 = gi & 7;
            cpa16(sbase + row * 144 + c16 * 16,
                  W + (size_t)(n0 + row) * ldw + k0 + c16 * 8, 16);
        }
    };
    auto stageA = [&](int c) {
        const uint32_t sbase = sb0 + (c % NSTAGE) * 2 * TILEB;
        const int k0 = c * BK;
#pragma unroll
        for (int g = 0; g < 2; g++) {
            int gi = tid + g * 256;
            int row = gi >> 3, c16 = gi & 7;
            int am = m0 + row;
            size_t aoff;
            int sz = 16;
            if (SHIFT) {
                int t = am % T;
                if (t == 0) { sz = 0; aoff = (size_t)am * lda + k0 + c16 * 8; }
                else aoff = (size_t)(am - 1) * lda + k0 + c16 * 8;
            } else {
                aoff = (size_t)am * lda + k0 + c16 * 8;
            }
            cpa16(sbase + row * 144 + c16 * 16, A + aoff, sz);
        }
    };

    if (WPRE) {
        stageW(0); cpa_commit();                    // G: W0
        if (nchunk > 1) { stageW(1); cpa_commit(); }  // G: W1
        cudaGridDependencySynchronize();
        stageA(0); cpa_commit();                    // G: A0
        if (nchunk > 1) { stageA(1); cpa_commit(); }  // G: A1
    } else {
        cudaGridDependencySynchronize();
        stageA(0); stageW(0); cpa_commit();         // G: AW0
        if (nchunk > 1) { stageA(1); stageW(1); cpa_commit(); }  // G: AW1
    }

    const int w = tid >> 5;
    const int wm = w >> 2;
    const int wn = w & 3;

    wmma::fragment<wmma::accumulator, 16, 16, 16, float> acc[2];
    wmma::fill_fragment(acc[0], 0.f);
    wmma::fill_fragment(acc[1], 0.f);

    for (int c = 0; c < nchunk; c++) {
        if (c + 1 < nchunk) {
            asm volatile("cp.async.wait_group 1;");   // retire through chunk c's groups
        } else {
            asm volatile("cp.async.wait_group 0;");
        }
        __syncthreads();      // chunk c visible; prior compute on buf (c+2)%3 done
        if (c + 2 < nchunk) { stageA(c + 2); stageW(c + 2); cpa_commit(); }
        char* bb = sm + (c % NSTAGE) * 2 * TILEB;
        const __half* tA = reinterpret_cast<const __half*>(bb);
        const __half* tW = reinterpret_cast<const __half*>(bb + TILEB);
#pragma unroll
        for (int ks = 0; ks < 4; ks++) {
            wmma::fragment<wmma::matrix_b, 16, 16, 16, __half, wmma::col_major> bh;
            wmma::load_matrix_sync(bh, &tW[(wn * 16) * LDTE + ks * 16], LDTE);
            wmma::fragment<wmma::matrix_a, 16, 16, 16, __half, wmma::row_major> ah[2];
            wmma::load_matrix_sync(ah[0], &tA[(wm * 32) * LDTE + ks * 16], LDTE);
            wmma::load_matrix_sync(ah[1], &tA[(wm * 32 + 16) * LDTE + ks * 16], LDTE);
            wmma::mma_sync(acc[0], ah[0], bh, acc[0]);
            wmma::mma_sync(acc[1], ah[1], bh, acc[1]);
        }
    }
    __syncthreads();   // all warps done before epilogue aliases smem

    float* Cs = reinterpret_cast<float*>(sm);
    wmma::store_matrix_sync(&Cs[(wm * 32) * LDTE + wn * 16], acc[0], LDTE, wmma::mem_row_major);
    wmma::store_matrix_sync(&Cs[(wm * 32 + 16) * LDTE + wn * 16], acc[1], LDTE, wmma::mem_row_major);
    __syncthreads();

#pragma unroll
    for (int i = tid * 4; i < BM * BN; i += 1024) {
        int r = i >> 6, cc = i & 63;
        int m = m0 + r, n = n0 + cc;
        float4 v = *reinterpret_cast<const float4*>(&Cs[r * LDTE + cc]);
        if (BIAS) {
            float4 bv = *reinterpret_cast<const float4*>(&bias[n]);
            v.x += bv.x; v.y += bv.y; v.z += bv.z; v.w += bv.w;
        }
        if (RES) {
            float4 rv = *reinterpret_cast<const float4*>(&res[(size_t)m * ldc + n]);
            v.x += rv.x; v.y += rv.y; v.z += rv.z; v.w += rv.w;
        }
        if (RELU) {
            v.x = fmaxf(v.x, 0.f); v.y = fmaxf(v.y, 0.f);
            v.z = fmaxf(v.z, 0.f); v.w = fmaxf(v.w, 0.f);
        }
        if (EMIT32) *reinterpret_cast<float4*>(&C32[(size_t)m * ldc + n]) = v;
        if (EMITH) {
            *reinterpret_cast<__half2*>(&Ch[(size_t)m * ldc + n]) = __floats2half2_rn(v.x, v.y);
            *reinterpret_cast<__half2*>(&Ch[(size_t)m * ldc + n + 2]) = __floats2half2_rn(v.z, v.w);
        }
    }
}

// ---------------- attention (fp16 qkv in, fp16 ctx out) ----------------
__global__ void __launch_bounds__(256) attn_kernel(const __half* __restrict__ qkv,
                                                   __half* __restrict__ ctxh) {
    cudaGridDependencySynchronize();
    int bh = blockIdx.x;
    int b = bh / H;
    int h = bh % H;
    __shared__ float Ks[T][HD + 1];
    __shared__ float Vs[T][HD + 1];
    __shared__ float Qs[8][HD];
    __shared__ float Ps[8][T];
    int tid = threadIdx.x;
    int w = tid >> 5, lane = tid & 31;
    for (int i = tid; i < T * HD; i += 256) {
        int t = i >> 6, d = i & 63;
        size_t base = ((size_t)(b * T + t)) * (3 * D) + h * HD + d;
        Ks[t][d] = __half2float(qkv[base + D]);
        Vs[t][d] = __half2float(qkv[base + 2 * D]);
    }
    __syncthreads();
    for (int r = w; r < T; r += 8) {
        size_t qb = ((size_t)(b * T + r)) * (3 * D) + h * HD;
        Qs[w][lane] = __half2float(qkv[qb + lane]);
        Qs[w][lane + 32] = __half2float(qkv[qb + lane + 32]);
        __syncwarp();
        int k0 = lane, k1 = lane + 32;
        float s0 = -1e30f, s1 = -1e30f;
        if (k0 <= r) {
            float a = 0.f;
#pragma unroll
            for (int d = 0; d < HD; d++) a += Qs[w][d] * Ks[k0][d];
            s0 = a * 0.125f;
        }
        if (k1 <= r && k1 < T) {
            float a = 0.f;
#pragma unroll
            for (int d = 0; d < HD; d++) a += Qs[w][d] * Ks[k1][d];
            s1 = a * 0.125f;
        }
        float m = fmaxf(s0, s1);
#pragma unroll
        for (int o = 16; o; o >>= 1) m = fmaxf(m, __shfl_xor_sync(0xffffffffu, m, o));
        float e0 = (k0 <= r) ? __expf(s0 - m) : 0.f;
        float e1 = (k1 <= r && k1 < T) ? __expf(s1 - m) : 0.f;
        float ssum = e0 + e1;
#pragma unroll
        for (int o = 16; o; o >>= 1) ssum += __shfl_xor_sync(0xffffffffu, ssum, o);
        float inv = 1.f / ssum;
        Ps[w][k0] = e0 * inv;
        if (k1 < T) Ps[w][k1] = e1 * inv;
        __syncwarp();
        float a0 = 0.f, a1 = 0.f;
        for (int k = 0; k <= r; k++) {
            float p = Ps[w][k];
            a0 += p * Vs[k][lane];
            a1 += p * Vs[k][lane + 32];
        }
        size_t ob = ((size_t)(b * T + r)) * D + h * HD;
        ctxh[ob + lane] = __float2half_rn(a0);
        ctxh[ob + lane + 32] = __float2half_rn(a1);
        __syncwarp();
    }
}

// ---------------- layernorm ----------------
__global__ void __launch_bounds__(256) ln_kernel(const float* __restrict__ in,
                                                 const float* __restrict__ sc,
                                                 const float* __restrict__ bi,
                                                 float* __restrict__ out32,
                                                 __half* __restrict__ outh) {
    int row = blockIdx.x, tid = threadIdx.x;
    float scv = sc[tid];                 // params ready before producer; pre-sync load
    float biv = bi[tid];
    cudaGridDependencySynchronize();
    float v = in[(size_t)row * D + tid];
    float sum = v, sq = v * v;
#pragma unroll
    for (int o = 16; o; o >>= 1) {
        sum += __shfl_xor_sync(0xffffffffu, sum, o);
        sq += __shfl_xor_sync(0xffffffffu, sq, o);
    }
    __shared__ float r1[8], r2[8];
    int w = tid >> 5, lane = tid & 31;
    if (!lane) { r1[w] = sum; r2[w] = sq; }
    __syncthreads();
    if (w == 0) {
        float a = (lane < 8) ? r1[lane] : 0.f;
        float b2 = (lane < 8) ? r2[lane] : 0.f;
#pragma unroll
        for (int o = 4; o; o >>= 1) {
            a += __shfl_xor_sync(0xffffffffu, a, o);
            b2 += __shfl_xor_sync(0xffffffffu, b2, o);
        }
        if (!lane) { r1[0] = a; r2[0] = b2; }
    }
    __syncthreads();
    float mean = r1[0] * (1.f / 256.f);
    float var = r2[0] * (1.f / 256.f) - mean * mean;
    float o = (v - mean) * rsqrtf(var + EPS) * scv + biv;
    size_t idx = (size_t)row * D + tid;
    out32[idx] = o;
    outh[idx] = __float2half_rn(o);
}

// ---------------- u (scaled by 0.5) + c0 ----------------
__global__ void __launch_bounds__(256) u_kernel(const int* __restrict__ tokens,
                                                const float* __restrict__ cls_w,
                                                const float* __restrict__ cls_b,
                                                const float* __restrict__ fw2,
                                                const float* __restrict__ fb2,
                                                float* __restrict__ u,
                                                float* __restrict__ c0) {
    int bt0 = blockIdx.x * 8;
    int tid = threadIdx.x, w = tid >> 5, lane = tid & 31;
    __shared__ float ws[8][D];
    __shared__ int toksh[8];
    if (tid < 8) toksh[tid] = tokens[bt0 + tid];
    __syncthreads();
#pragma unroll
    for (int j = 0; j < 8; j++) ws[j][tid] = cls_w[(size_t)toksh[j] * D + tid];
    __syncthreads();
    {
        float s = 0.f;
        for (int d = lane; d < D; d += 32) s += fb2[d] * ws[w][d];
#pragma unroll
        for (int o = 16; o; o >>= 1) s += __shfl_xor_sync(0xffffffffu, s, o);
        if (!lane) c0[bt0 + w] = s + cls_b[toksh[w]];
    }
    float acc[8] = {};
    for (int d = 0; d < D; d++) {
        float f = fw2[(size_t)d * D + tid];
#pragma unroll
        for (int j = 0; j < 8; j++) acc[j] += ws[j][d] * f;
    }
#pragma unroll
    for (int j = 0; j < 8; j++) u[(size_t)(bt0 + j) * D + tid] = 0.5f * acc[j];
}

// ---------------- final: half2 gelu-dot + sigmoid; pproj/u/c0 staged pre-gridsync ------
constexpr int PT = 64;
constexpr int TT = 20;
constexpr int PROW = 132;
constexpr int SMEM_FINAL = (PT * PROW + TT * 128 * 2 + TT) * 4;  // 54,352 B

__global__ void __launch_bounds__(512, 2) final_kernel(const float* __restrict__ pproj,
                                                       const float* __restrict__ cproj,
                                                       const float* __restrict__ u,
                                                       const float* __restrict__ c0,
                                                       float* __restrict__ out) {
    extern __shared__ char smb[];
    __half2* pps = reinterpret_cast<__half2*>(smb);          // [PT][PROW] (p-major)
    __half2* cps = pps + PT * PROW;                          // [TT][128]
    __half2* us = cps + TT * 128;                            // [TT][128]
    float* c0s = reinterpret_cast<float*>(us + TT * 128);    // [TT]
    int b = blockIdx.x;
    int p0 = blockIdx.y * PT;
    int tb0 = blockIdx.z * TT;
    int tid = threadIdx.x;

    // pre-gridsync: pproj, u, c0 are complete before this kernel launches (event joins)
    for (int i = tid; i < PT * (D / 2); i += 512) {
        int p = i >> 7;
        int e2 = i & 127;
        float2 v = *reinterpret_cast<const float2*>(&pproj[((size_t)(b * P + p0 + p)) * D + e2 * 2]);
        pps[p * PROW + e2] = __floats2half2_rn(v.x, v.y);
    }
    for (int i = tid; i < TT * (D / 2); i += 512) {
        int t = i >> 7;
        int e2 = i & 127;
        float2 uv = *reinterpret_cast<const float2*>(&u[((size_t)(b * T + tb0 + t)) * D + e2 * 2]);
        us[t * 128 + e2] = __floats2half2_rn(uv.x, uv.y);
    }
    if (tid < TT) c0s[tid] = c0[b * T + tb0 + tid];

    cudaGridDependencySynchronize();   // wait for cproj

    for (int i = tid; i < TT * (D / 2); i += 512) {
        int t = i >> 7;
        int e2 = i & 127;
        float2 cv = *reinterpret_cast<const float2*>(&cproj[((size_t)(b * T + tb0 + t)) * D + e2 * 2]);
        cps[t * 128 + e2] = __floats2half2_rn(cv.x, cv.y);
    }
    __syncthreads();

    const __half2 C1 = __float2half2_rn(0.035677408f);
    const __half2 C2 = __float2half2_rn(0.7978845608f);
    const __half2 HZ = __float2half2_rn(0.f);

    int pl = tid & 63;
    int tg = tid >> 6;
    const int nt = (tg < TT - 16) ? 3 : 2;
    float acc[3] = {};
    __half2 hacc[3] = {HZ, HZ, HZ};
    const float4* perow = reinterpret_cast<const float4*>(pps + pl * PROW);

    for (int e4 = 0; e4 < 32; e4++) {
        float4 pef = perow[e4];
        const __half2* pe = reinterpret_cast<const __half2*>(&pef);
#pragma unroll 3
        for (int i = 0; i < 3; i++) {
            if (i < nt) {
                int t = tg + 8 * i;
                float4 cpf = *reinterpret_cast<const float4*>(cps + t * 128 + e4 * 4);
                float4 uuf = *reinterpret_cast<const float4*>(us + t * 128 + e4 * 4);
                const __half2* cp = reinterpret_cast<const __half2*>(&cpf);
                const __half2* uu = reinterpret_cast<const __half2*>(&uuf);
#pragma unroll
                for (int j = 0; j < 4; j++) {
                    __half2 x2 = __hadd2(pe[j], cp[j]);
                    __half2 sq = __hmul2(x2, x2);
                    __half2 t1 = __hfma2(C1, sq, C2);
                    __half2 th = htanh2(__hmul2(x2, t1));
                    __half2 w = __hmul2(x2, uu[j]);    // uu = 0.5*u
                    hacc[i] = __hadd2(hacc[i], __hfma2(w, th, w));
                }
            }
        }
        if ((e4 & 3) == 3) {
#pragma unroll 3
            for (int i = 0; i < 3; i++) {
                if (i < nt) {
                    float2 f = __half22float2(hacc[i]);
                    acc[i] += f.x + f.y;
                    hacc[i] = HZ;
                }
            }
        }
    }
    int p = p0 + pl;
#pragma unroll 3
    for (int i = 0; i < 3; i++) {
        if (i < nt) {
            int t = tg + 8 * i;
            float logit = acc[i] + c0s[t];
            out[((size_t)(b * P + p)) * T + tb0 + t] = 1.f / (1.f + __expf(-logit));
        }
    }
}

// ---------------- PDL launch helper ----------------
template <typename F, typename... AA>
static inline void launch_pdl(F k, dim3 g, dim3 b, size_t smem, AA... args) {
    cudaLaunchConfig_t cfg = {};
    cfg.gridDim = g;
    cfg.blockDim = b;
    cfg.dynamicSmemBytes = smem;
    cfg.stream = 0;
    cudaLaunchAttribute at[1];
    at[0].id = cudaLaunchAttributeProgrammaticStreamSerialization;
    at[0].val.programmaticStreamSerializationAllowed = 1;
    cfg.attrs = at;
    cfg.numAttrs = 1;
    cudaLaunchKernelEx(&cfg, k, args...);
}

// ---------------- host ----------------
extern "C" void kernel_launch(void* const* d_in, const int* in_sizes, int n_in,
                              void* d_out, int out_size) {
    const float* patches = (const float*)d_in[0];
    const int* tokens = (const int*)d_in[1];
    const float* tok_emb = (const float*)d_in[2];
    const float* pos_emb = (const float*)d_in[3];
    const float* qkv_w = (const float*)d_in[4];
    const float* qkv_b = (const float*)d_in[5];
    const float* out_w = (const float*)d_in[6];
    const float* out_b = (const float*)d_in[7];
    const float* ln1_s = (const float*)d_in[8];
    const float* ln1_b = (const float*)d_in[9];
    const float* w1 = (const float*)d_in[10];
    const float* b1 = (const float*)d_in[11];
    const float* w2 = (const float*)d_in[12];
    const float* b2 = (const float*)d_in[13];
    const float* ln2_s = (const float*)d_in[14];
    const float* ln2_b = (const float*)d_in[15];
    const float* fus_w1 = (const float*)d_in[16];
    const float* fus_b1 = (const float*)d_in[17];
    const float* fus_w2 = (const float*)d_in[18];
    const float* fus_b2 = (const float*)d_in[19];
    const float* cls_w = (const float*)d_in[20];
    const float* cls_b = (const float*)d_in[21];
    float* out = (float*)d_out;

    float *px, *py, *ppp, *pcp, *pu, *pc0;
    cudaGetSymbolAddress((void**)&px, g_x);
    cudaGetSymbolAddress((void**)&py, g_y);
    cudaGetSymbolAddress((void**)&ppp, g_pproj);
    cudaGetSymbolAddress((void**)&pcp, g_cproj);
    cudaGetSymbolAddress((void**)&pu, g_u);
    cudaGetSymbolAddress((void**)&pc0, g_c0);

    __half *pxh, *pqkvh, *pch, *phh, *pph, *pqwh, *powh, *pw1h, *pw2h, *pfwh;
    cudaGetSymbolAddress((void**)&pxh, g_xh);
    cudaGetSymbolAddress((void**)&pqkvh, g_qkvh);
    cudaGetSymbolAddress((void**)&pch, g_ctxh);
    cudaGetSymbolAddress((void**)&phh, g_hh);
    cudaGetSymbolAddress((void**)&pph, g_ph);
    cudaGetSymbolAddress((void**)&pqwh, g_qkvwh);
    cudaGetSymbolAddress((void**)&powh, g_outwh);
    cudaGetSymbolAddress((void**)&pw1h, g_w1h);
    cudaGetSymbolAddress((void**)&pw2h, g_w2h);
    cudaGetSymbolAddress((void**)&pfwh, g_fw1h);

    // instantiation aliases (WPRE = W ready before PDL predecessor)
    auto kQKV0  = gemm_fp16<true, false, false, false, true, false, false>;
    auto kQKV1  = gemm_fp16<true, false, false, false, true, false, true>;
    auto kOUT   = gemm_fp16<true, true, false, true, false, false, true>;
    auto kFFN1  = gemm_fp16<true, false, true, false, true, false, true>;
    auto kPPROJ = gemm_fp16<false, false, false, true, false, false, true>;
    auto kCPROJ = gemm_fp16<true, false, false, true, false, true, true>;

    cudaFuncSetAttribute(final_kernel, cudaFuncAttributeMaxDynamicSharedMemorySize, SMEM_FINAL);
    cudaFuncSetAttribute(kQKV0, cudaFuncAttributeMaxDynamicSharedMemorySize, GEMM_SMEM);
    cudaFuncSetAttribute(kQKV1, cudaFuncAttributeMaxDynamicSharedMemorySize, GEMM_SMEM);
    cudaFuncSetAttribute(kOUT, cudaFuncAttributeMaxDynamicSharedMemorySize, GEMM_SMEM);
    cudaFuncSetAttribute(kFFN1, cudaFuncAttributeMaxDynamicSharedMemorySize, GEMM_SMEM);
    cudaFuncSetAttribute(kPPROJ, cudaFuncAttributeMaxDynamicSharedMemorySize, GEMM_SMEM);
    cudaFuncSetAttribute(kCPROJ, cudaFuncAttributeMaxDynamicSharedMemorySize, GEMM_SMEM);

    static cudaStream_t s1 = nullptr, s2 = nullptr;
    static cudaEvent_t ev0 = nullptr, ev1 = nullptr, ev2 = nullptr, ev3 = nullptr;
    if (!s1) {
        cudaStreamCreateWithFlags(&s1, cudaStreamNonBlocking);
        cudaStreamCreateWithFlags(&s2, cudaStreamNonBlocking);
        cudaEventCreateWithFlags(&ev0, cudaEventDisableTiming);
        cudaEventCreateWithFlags(&ev1, cudaEventDisableTiming);
        cudaEventCreateWithFlags(&ev2, cudaEventDisableTiming);
        cudaEventCreateWithFlags(&ev3, cudaEventDisableTiming);
    }

    // launch 1: prep_main (embed + L0 qkv weights)
    prep_main_kernel<<<512, 256>>>(qkv_w, tokens, tok_emb, pos_emb);

    // fork side branches
    cudaEventRecord(ev0, 0);
    cudaStreamWaitEvent(s1, ev0, 0);
    cudaStreamWaitEvent(s2, ev0, 0);

    // s1: fusion prep + pproj            (launches 2, 3)
    prep_fus_kernel<<<1024, 256, 0, s1>>>(fus_w1, patches);
    kPPROJ<<<dim3(D / BN, B * P / BM), 256, GEMM_SMEM, s1>>>(
        pph, DINO, pfwh, DINO + D, nullptr, nullptr, ppp, nullptr, D, DINO);
    cudaEventRecord(ev1, s1);

    // launch 4: qkv GEMM layer 0 (ncu target); launch 5: attn layer 0
    launch_pdl(kQKV0, dim3(3 * D / BN, M_ENC / BM), dim3(256), (size_t)GEMM_SMEM,
               (const __half*)pxh, (int)D, (const __half*)pqwh, (int)D,
               (const float*)qkv_b, (const float*)nullptr,
               (float*)nullptr, (__half*)pqkvh, (int)(3 * D), (int)D);
    launch_pdl(attn_kernel, dim3(B * H), dim3(256), (size_t)0,
               (const __half*)pqkvh, (__half*)pch);

    // s2: remaining encoder weights + u/c0 (concurrent with qkv/attn)
    prep_rest_kernel<<<1024, 256, 0, s2>>>(qkv_w, out_w, w1, w2);
    cudaEventRecord(ev3, s2);
    u_kernel<<<M_ENC / 8, 256, 0, s2>>>(tokens, cls_w, cls_b, fus_w2, fus_b2, pu, pc0);
    cudaEventRecord(ev2, s2);

    for (int l = 0; l < L; l++) {
        if (l > 0) {
            launch_pdl(kQKV1, dim3(3 * D / BN, M_ENC / BM), dim3(256), (size_t)GEMM_SMEM,
                       (const __half*)pxh, (int)D, (const __half*)(pqwh + (size_t)l * 3 * D * D), (int)D,
                       (const float*)(qkv_b + (size_t)l * 3 * D), (const float*)nullptr,
                       (float*)nullptr, (__half*)pqkvh, (int)(3 * D), (int)D);
            launch_pdl(attn_kernel, dim3(B * H), dim3(256), (size_t)0,
                       (const __half*)pqkvh, (__half*)pch);
        }
        if (l == 0) cudaStreamWaitEvent(0, ev3, 0);   // need out_w/w1/w2 fp16 from s2
        // outproj + residual
        launch_pdl(kOUT, dim3(D / BN, M_ENC / BM), dim3(256), (size_t)GEMM_SMEM,
                   (const __half*)pch, (int)D, (const __half*)(powh + (size_t)l * D * D), (int)D,
                   (const float*)(out_b + (size_t)l * D), (const float*)px,
                   (float*)py, (__half*)nullptr, (int)D, (int)D);
        launch_pdl(ln_kernel, dim3(M_ENC), dim3(256), (size_t)0,
                   (const float*)py, (const float*)(ln1_s + (size_t)l * D), (const float*)(ln1_b + (size_t)l * D),
                   (float*)px, (__half*)pxh);
        // ffn1 (relu, fp16 out)
        launch_pdl(kFFN1, dim3(DFF / BN, M_ENC / BM), dim3(256), (size_t)GEMM_SMEM,
                   (const __half*)pxh, (int)D, (const __half*)(pw1h + (size_t)l * DFF * D), (int)D,
                   (const float*)(b1 + (size_t)l * DFF), (const float*)nullptr,
                   (float*)nullptr, (__half*)phh, (int)DFF, (int)D);
        // ffn2 + residual
        launch_pdl(kOUT, dim3(D / BN, M_ENC / BM), dim3(256), (size_t)GEMM_SMEM,
                   (const __half*)phh, (int)DFF, (const __half*)(pw2h + (size_t)l * D * DFF), (int)DFF,
                   (const float*)(b2 + (size_t)l * D), (const float*)px,
                   (float*)py, (__half*)nullptr, (int)D, (int)DFF);
        launch_pdl(ln_kernel, dim3(M_ENC), dim3(256), (size_t)0,
                   (const float*)py, (const float*)(ln2_s + (size_t)l * D), (const float*)(ln2_b + (size_t)l * D),
                   (float*)px, (__half*)pxh);
    }

    // join: cproj (needs fus_w1 fp16 from s1); shift folded into staging
    cudaStreamWaitEvent(0, ev1, 0);
    launch_pdl(kCPROJ, dim3(D / BN, M_ENC / BM), dim3(256), (size_t)GEMM_SMEM,
               (const __half*)pxh, (int)D, (const __half*)(pfwh + DINO), (int)(DINO + D),
               (const float*)fus_b1, (const float*)nullptr,
               (float*)pcp, (__half*)nullptr, (int)D, (int)D);

    cudaStreamWaitEvent(0, ev2, 0);
    launch_pdl(final_kernel, dim3(B, P / PT, T / TT), dim3(512), (size_t)SMEM_FINAL,
               (const float*)ppp, (const float*)pcp, (const float*)pu, (const float*)pc0,
               (float*)out);
}